// round 4
// baseline (speedup 1.0000x reference)
#include <cuda_runtime.h>
#include <cstddef>

#define NN   20000
#define EE   320000
#define ELL  100000
#define ET   (EE + NN)          // 340000 edges incl. self loops
#define INF_ 256
#define HIDC 128
#define OUTC 128
#define HH   4
#define C1   (HH * HIDC)        // 512

// ---------------- scratch (device globals: allocation-free) ----------------
__device__ float g_xl1[(size_t)NN * C1];
__device__ float g_xr1[(size_t)NN * C1];
__device__ float g_out1[(size_t)NN * C1];       // agg -> z1 (gelu in-place)
__device__ float g_logits1[(size_t)ET * HH];
__device__ int   g_max1[NN * HH];
__device__ float g_sum1[NN * HH];
__device__ float g_xl2[(size_t)NN * OUTC];
__device__ float g_xr2[(size_t)NN * OUTC];
__device__ float g_out2[(size_t)NN * OUTC];     // agg -> z2
__device__ float g_logits2[ET];
__device__ int   g_max2[NN];
__device__ float g_sum2[NN];
__device__ float g_h[(size_t)ELL * HIDC];       // decoder hidden (post-gelu)

// ---------------- helpers ----------------
__device__ __forceinline__ float lrelu(float x) { return x >= 0.f ? x : 0.2f * x; }

__device__ __forceinline__ float gelu_t(float x) {
    float x3 = x * x * x;
    return 0.5f * x * (1.f + tanhf(0.7978845608028654f * (x + 0.044715f * x3)));
}

__device__ __forceinline__ int fkey(float f) {
    int i = __float_as_int(f);
    return i >= 0 ? i : (i ^ 0x7fffffff);
}
__device__ __forceinline__ float keyf(int i) {
    return __int_as_float(i >= 0 ? i : (i ^ 0x7fffffff));
}

__device__ __forceinline__ void red_add_v4(float* p, float4 v) {
    asm volatile("red.global.add.v4.f32 [%0], {%1,%2,%3,%4};"
                 :: "l"(p), "f"(v.x), "f"(v.y), "f"(v.z), "f"(v.w) : "memory");
}

__device__ __forceinline__ float tf32_rd(float x) {
    unsigned u;
    asm("cvt.rna.tf32.f32 %0, %1;" : "=r"(u) : "f"(x));
    return __uint_as_float(u);
}

__device__ __forceinline__ void mma_tf32(float d[4], const float a[4], const float b[2]) {
    asm volatile(
        "mma.sync.aligned.m16n8k8.row.col.f32.tf32.tf32.f32 "
        "{%0,%1,%2,%3}, {%4,%5,%6,%7}, {%8,%9}, {%0,%1,%2,%3};\n"
        : "+f"(d[0]), "+f"(d[1]), "+f"(d[2]), "+f"(d[3])
        : "r"(__float_as_uint(a[0])), "r"(__float_as_uint(a[1])),
          "r"(__float_as_uint(a[2])), "r"(__float_as_uint(a[3])),
          "r"(__float_as_uint(b[0])), "r"(__float_as_uint(b[1])));
}

// ---------------- init ----------------
__global__ void init_kernel() {
    int i = blockIdx.x * blockDim.x + threadIdx.x;
    if (i < NN * C1)   g_out1[i] = 0.f;
    if (i < NN * OUTC) g_out2[i] = 0.f;
    if (i < NN * HH) { g_max1[i] = (int)0x80000000; g_sum1[i] = 0.f; }
    if (i < NN)      { g_max2[i] = (int)0x80000000; g_sum2[i] = 0.f; }
}

// ---------------- tensor-core GEMM (tf32 x3, fp32-level accuracy) -----------
// 128x128 CTA tile, BK=16, 256 threads, 8 warps of 64x32 warp tiles.
// MODE 0: C{0,1} = A @ B{0,1} + bias{0,1}  (dual-B; grid.x = 2*Nc/128)
// MODE 1: C0 = gelu([A[gidx[r]] | A[gidx[ELL+r]]] @ B0 + bias0)   (decoder)
template<int MODE>
__global__ __launch_bounds__(256) void gemm_tc(
    const float* __restrict__ A, const int* __restrict__ gidx,
    const float* __restrict__ B0, const float* __restrict__ B1,
    const float* __restrict__ bias0, const float* __restrict__ bias1,
    float* __restrict__ C0, float* __restrict__ C1p,
    int M, int K, int Nc)
{
    __shared__ float As_hi[128][20];
    __shared__ float As_lo[128][20];
    __shared__ float Bs_hi[16][136];
    __shared__ float Bs_lo[16][136];

    int nb  = Nc >> 7;
    int mat = (blockIdx.x >= nb) ? 1 : 0;
    int bn  = (blockIdx.x - mat * nb) << 7;
    int bm  = blockIdx.y << 7;

    const float* B    = mat ? B1 : B0;
    const float* bias = mat ? bias1 : bias0;
    float*       C    = mat ? C1p : C0;

    int tid  = threadIdx.x;
    int lane = tid & 31, warp = tid >> 5;
    int wm = (warp >> 2) << 6;   // 0 or 64
    int wn = (warp & 3) << 5;    // 0..96
    int grp = lane >> 2, tg = lane & 3;

    // A loader: row = tid>>1, two float4 at k-off = (tid&1)*8 + {0,4}
    int a_r = tid >> 1;
    int a_k = (tid & 1) << 3;
    bool a_ok = (bm + a_r) < M;
    const float* aptr0;
    const float* aptr1 = nullptr;
    if (MODE == 0) {
        aptr0 = A + (size_t)(bm + a_r) * K;
    } else {
        int r = a_ok ? (bm + a_r) : 0;
        aptr0 = A + (size_t)gidx[r] * OUTC;
        aptr1 = A + (size_t)gidx[ELL + r] * OUTC;
    }
    // B loader: row = tid>>4, two float4 at col-off = (tid&15)*8 + {0,4}
    int b_r = tid >> 4;
    int b_c = (tid & 15) << 3;
    const float* bptr = B + (size_t)b_r * Nc + bn + b_c;

    float acc[4][4][4];
#pragma unroll
    for (int i = 0; i < 4; i++)
#pragma unroll
        for (int j = 0; j < 4; j++)
#pragma unroll
            for (int q = 0; q < 4; q++) acc[i][j][q] = 0.f;

    float4 ra[2], rb[2];
    const float4 zero4 = make_float4(0.f, 0.f, 0.f, 0.f);

    auto loadA = [&](int k0, int s) -> float4 {
        if (!a_ok) return zero4;
        int k = k0 + a_k + s * 4;
        if (MODE == 0) return *(const float4*)(aptr0 + k);
        return (k < OUTC) ? *(const float4*)(aptr0 + k)
                          : *(const float4*)(aptr1 + (k - OUTC));
    };

    // preload k-tile 0
#pragma unroll
    for (int s = 0; s < 2; s++) ra[s] = loadA(0, s);
#pragma unroll
    for (int s = 0; s < 2; s++) rb[s] = *(const float4*)(bptr + s * 4);

    auto storeSmem = [&]() {
#pragma unroll
        for (int s = 0; s < 2; s++) {
            int kk = a_k + s * 4;
            float v[4] = {ra[s].x, ra[s].y, ra[s].z, ra[s].w};
#pragma unroll
            for (int c = 0; c < 4; c++) {
                float h = tf32_rd(v[c]);
                As_hi[a_r][kk + c] = h;
                As_lo[a_r][kk + c] = tf32_rd(v[c] - h);
            }
        }
#pragma unroll
        for (int s = 0; s < 2; s++) {
            int cc = b_c + s * 4;
            float v[4] = {rb[s].x, rb[s].y, rb[s].z, rb[s].w};
#pragma unroll
            for (int c = 0; c < 4; c++) {
                float h = tf32_rd(v[c]);
                Bs_hi[b_r][cc + c] = h;
                Bs_lo[b_r][cc + c] = tf32_rd(v[c] - h);
            }
        }
    };

    storeSmem();
    __syncthreads();

    int nkt = K >> 4;
    for (int kt = 0; kt < nkt; kt++) {
        bool more = (kt + 1) < nkt;
        if (more) {
            int k0 = (kt + 1) << 4;
#pragma unroll
            for (int s = 0; s < 2; s++) ra[s] = loadA(k0, s);
            const float* bp = bptr + (size_t)k0 * Nc;
#pragma unroll
            for (int s = 0; s < 2; s++) rb[s] = *(const float4*)(bp + s * 4);
        }
#pragma unroll
        for (int ks = 0; ks < 2; ks++) {
            int kb = ks << 3;
            float ahi[4][4], alo[4][4];
#pragma unroll
            for (int i = 0; i < 4; i++) {
                int r0 = wm + (i << 4) + grp;
                ahi[i][0] = As_hi[r0][kb + tg];
                ahi[i][1] = As_hi[r0 + 8][kb + tg];
                ahi[i][2] = As_hi[r0][kb + tg + 4];
                ahi[i][3] = As_hi[r0 + 8][kb + tg + 4];
                alo[i][0] = As_lo[r0][kb + tg];
                alo[i][1] = As_lo[r0 + 8][kb + tg];
                alo[i][2] = As_lo[r0][kb + tg + 4];
                alo[i][3] = As_lo[r0 + 8][kb + tg + 4];
            }
            float bhi[4][2], blo[4][2];
#pragma unroll
            for (int j = 0; j < 4; j++) {
                int c = wn + (j << 3) + grp;
                bhi[j][0] = Bs_hi[kb + tg][c];
                bhi[j][1] = Bs_hi[kb + tg + 4][c];
                blo[j][0] = Bs_lo[kb + tg][c];
                blo[j][1] = Bs_lo[kb + tg + 4][c];
            }
#pragma unroll
            for (int i = 0; i < 4; i++)
#pragma unroll
                for (int j = 0; j < 4; j++) {
                    mma_tf32(acc[i][j], ahi[i], bhi[j]);
                    mma_tf32(acc[i][j], alo[i], bhi[j]);
                    mma_tf32(acc[i][j], ahi[i], blo[j]);
                }
        }
        __syncthreads();
        if (more) {
            storeSmem();
            __syncthreads();
        }
    }

    // epilogue
#pragma unroll
    for (int j = 0; j < 4; j++) {
        int c = bn + wn + (j << 3) + (tg << 1);
        float bv0 = bias[c], bv1 = bias[c + 1];
#pragma unroll
        for (int i = 0; i < 4; i++) {
            int r0 = bm + wm + (i << 4) + grp;
            float2 v0 = make_float2(acc[i][j][0] + bv0, acc[i][j][1] + bv1);
            float2 v1 = make_float2(acc[i][j][2] + bv0, acc[i][j][3] + bv1);
            if (MODE == 1) {
                v0.x = gelu_t(v0.x); v0.y = gelu_t(v0.y);
                v1.x = gelu_t(v1.x); v1.y = gelu_t(v1.y);
            }
            if (r0 < M)     *(float2*)(C + (size_t)r0 * Nc + c) = v0;
            if (r0 + 8 < M) *(float2*)(C + (size_t)(r0 + 8) * Nc + c) = v1;
        }
    }
}

// ---------------- layer 1 edge kernels (H=4, C=128) ------------------------
__global__ __launch_bounds__(256) void logits1_kernel(const int* __restrict__ ei,
                                                      const float* __restrict__ att)
{
    int gw = (blockIdx.x * blockDim.x + threadIdx.x) >> 5;
    if (gw >= ET) return;
    int lane = threadIdx.x & 31;
    int src, dst;
    if (gw < EE) { src = ei[gw]; dst = ei[EE + gw]; }
    else         { src = dst = gw - EE; }

    const float4* pl = (const float4*)(g_xl1 + (size_t)src * C1);
    const float4* pr = (const float4*)(g_xr1 + (size_t)dst * C1);
    const float4* pa = (const float4*)att;

    float res[HH];
#pragma unroll
    for (int h = 0; h < HH; h++) {
        int f = h * 32 + lane;
        float4 l = pl[f], r = pr[f], a = pa[f];
        float p = lrelu(l.x + r.x) * a.x + lrelu(l.y + r.y) * a.y +
                  lrelu(l.z + r.z) * a.z + lrelu(l.w + r.w) * a.w;
        p += __shfl_down_sync(0xffffffffu, p, 16);
        p += __shfl_down_sync(0xffffffffu, p, 8);
        p += __shfl_down_sync(0xffffffffu, p, 4);
        p += __shfl_down_sync(0xffffffffu, p, 2);
        p += __shfl_down_sync(0xffffffffu, p, 1);
        res[h] = p;
    }
    if (lane == 0) {
#pragma unroll
        for (int h = 0; h < HH; h++) {
            g_logits1[(size_t)gw * HH + h] = res[h];
            atomicMax(&g_max1[dst * HH + h], fkey(res[h]));
        }
    }
}

// scatter unnormalized exp-weighted messages; accumulate denominator on the fly
__global__ __launch_bounds__(256) void scatter1_kernel(const int* __restrict__ ei)
{
    int gw = (blockIdx.x * blockDim.x + threadIdx.x) >> 5;
    if (gw >= ET) return;
    int lane = threadIdx.x & 31;
    int src, dst;
    if (gw < EE) { src = ei[gw]; dst = ei[EE + gw]; }
    else         { src = dst = gw - EE; }

    const float4* pl = (const float4*)(g_xl1 + (size_t)src * C1);
    float* pd = g_out1 + (size_t)dst * C1;
    float a[HH];
#pragma unroll
    for (int h = 0; h < HH; h++) {
        a[h] = __expf(g_logits1[(size_t)gw * HH + h] - keyf(g_max1[dst * HH + h]));
        if (lane == 0) atomicAdd(&g_sum1[dst * HH + h], a[h]);
    }
#pragma unroll
    for (int h = 0; h < HH; h++) {
        int f = h * 32 + lane;
        float4 v = pl[f];
        v.x *= a[h]; v.y *= a[h]; v.z *= a[h]; v.w *= a[h];
        red_add_v4(pd + f * 4, v);
    }
}

// divide by softmax denom, add bias, gelu
__global__ __launch_bounds__(256) void gelu1_kernel(const float* __restrict__ bias1)
{
    int i = blockIdx.x * blockDim.x + threadIdx.x;
    if (i >= NN * C1) return;
    int n = i >> 9, h = (i >> 7) & 3;
    float v = g_out1[i] / g_sum1[(n << 2) + h] + bias1[i & (C1 - 1)];
    g_out1[i] = gelu_t(v);
}

// ---------------- layer 2 edge kernels (H=1, C=128) ------------------------
__global__ __launch_bounds__(256) void logits2_kernel(const int* __restrict__ ei,
                                                      const float* __restrict__ att2)
{
    int gw = (blockIdx.x * blockDim.x + threadIdx.x) >> 5;
    if (gw >= ET) return;
    int lane = threadIdx.x & 31;
    int src, dst;
    if (gw < EE) { src = ei[gw]; dst = ei[EE + gw]; }
    else         { src = dst = gw - EE; }

    const float4* pl = (const float4*)(g_xl2 + (size_t)src * OUTC);
    const float4* pr = (const float4*)(g_xr2 + (size_t)dst * OUTC);
    float4 l = pl[lane], r = pr[lane], a = ((const float4*)att2)[lane];
    float p = lrelu(l.x + r.x) * a.x + lrelu(l.y + r.y) * a.y +
              lrelu(l.z + r.z) * a.z + lrelu(l.w + r.w) * a.w;
    p += __shfl_down_sync(0xffffffffu, p, 16);
    p += __shfl_down_sync(0xffffffffu, p, 8);
    p += __shfl_down_sync(0xffffffffu, p, 4);
    p += __shfl_down_sync(0xffffffffu, p, 2);
    p += __shfl_down_sync(0xffffffffu, p, 1);
    if (lane == 0) {
        g_logits2[gw] = p;
        atomicMax(&g_max2[dst], fkey(p));
    }
}

__global__ __launch_bounds__(256) void scatter2_kernel(const int* __restrict__ ei)
{
    int gw = (blockIdx.x * blockDim.x + threadIdx.x) >> 5;
    if (gw >= ET) return;
    int lane = threadIdx.x & 31;
    int src, dst;
    if (gw < EE) { src = ei[gw]; dst = ei[EE + gw]; }
    else         { src = dst = gw - EE; }

    float a = __expf(g_logits2[gw] - keyf(g_max2[dst]));
    if (lane == 0) atomicAdd(&g_sum2[dst], a);
    const float4* pl = (const float4*)(g_xl2 + (size_t)src * OUTC);
    float4 v = pl[lane];
    v.x *= a; v.y *= a; v.z *= a; v.w *= a;
    red_add_v4(g_out2 + (size_t)dst * OUTC + lane * 4, v);
}

__global__ __launch_bounds__(256) void bias2_kernel(const float* __restrict__ bias2)
{
    int i = blockIdx.x * blockDim.x + threadIdx.x;
    if (i >= NN * OUTC) return;
    g_out2[i] = g_out2[i] / g_sum2[i >> 7] + bias2[i & (OUTC - 1)];
}

// ---------------- decoder reduce: out = h . Wd2 + bd2 ----------------------
__global__ __launch_bounds__(256) void dec_reduce(const float* __restrict__ Wd2,
                                                  const float* __restrict__ bd2,
                                                  float* __restrict__ out)
{
    int m = (blockIdx.x * blockDim.x + threadIdx.x) >> 5;
    if (m >= ELL) return;
    int lane = threadIdx.x & 31;
    float4 h = *(const float4*)(g_h + (size_t)m * HIDC + lane * 4);
    float4 w = *(const float4*)(Wd2 + lane * 4);
    float p = h.x * w.x + h.y * w.y + h.z * w.z + h.w * w.w;
    p += __shfl_down_sync(0xffffffffu, p, 16);
    p += __shfl_down_sync(0xffffffffu, p, 8);
    p += __shfl_down_sync(0xffffffffu, p, 4);
    p += __shfl_down_sync(0xffffffffu, p, 2);
    p += __shfl_down_sync(0xffffffffu, p, 1);
    if (lane == 0) out[m] = p + bd2[0];
}

// ---------------- launch ----------------------------------------------------
extern "C" void kernel_launch(void* const* d_in, const int* in_sizes, int n_in,
                              void* d_out, int out_size)
{
    const float* x     = (const float*)d_in[0];
    const int*   ei    = (const int*)d_in[1];
    const int*   eli   = (const int*)d_in[2];
    const float* W_l1  = (const float*)d_in[3];
    const float* b_l1  = (const float*)d_in[4];
    const float* W_r1  = (const float*)d_in[5];
    const float* b_r1  = (const float*)d_in[6];
    const float* att1  = (const float*)d_in[7];
    const float* bias1 = (const float*)d_in[8];
    const float* W_l2  = (const float*)d_in[9];
    const float* b_l2  = (const float*)d_in[10];
    const float* W_r2  = (const float*)d_in[11];
    const float* b_r2  = (const float*)d_in[12];
    const float* att2  = (const float*)d_in[13];
    const float* bias2 = (const float*)d_in[14];
    const float* W_d1  = (const float*)d_in[15];
    const float* b_d1  = (const float*)d_in[16];
    const float* W_d2  = (const float*)d_in[17];
    const float* b_d2  = (const float*)d_in[18];
    float* out = (float*)d_out;

    float *xl1, *xr1, *out1, *xl2, *xr2, *out2, *hbuf;
    cudaGetSymbolAddress((void**)&xl1,  g_xl1);
    cudaGetSymbolAddress((void**)&xr1,  g_xr1);
    cudaGetSymbolAddress((void**)&out1, g_out1);
    cudaGetSymbolAddress((void**)&xl2,  g_xl2);
    cudaGetSymbolAddress((void**)&xr2,  g_xr2);
    cudaGetSymbolAddress((void**)&out2, g_out2);
    cudaGetSymbolAddress((void**)&hbuf, g_h);

    // 0) reset accumulators
    init_kernel<<<(NN * C1 + 255) / 256, 256>>>();

    // 1) layer-1 transforms (tensor core): xl1 = x@W_l1+b_l1, xr1 = x@W_r1+b_r1
    {
        dim3 grid(2 * (C1 / 128), (NN + 127) / 128);
        gemm_tc<0><<<grid, 256>>>(x, nullptr, W_l1, W_r1, b_l1, b_r1,
                                  xl1, xr1, NN, INF_, C1);
    }

    // 2) layer-1 attention
    int eb = ((ET * 32) + 255) / 256;
    logits1_kernel<<<eb, 256>>>(ei, att1);
    scatter1_kernel<<<eb, 256>>>(ei);
    gelu1_kernel<<<(NN * C1 + 255) / 256, 256>>>(bias1);

    // 3) layer-2 transforms (tensor core)
    {
        dim3 grid(2 * (OUTC / 128), (NN + 127) / 128);
        gemm_tc<0><<<grid, 256>>>(out1, nullptr, W_l2, W_r2, b_l2, b_r2,
                                  xl2, xr2, NN, C1, OUTC);
    }

    // 4) layer-2 attention
    logits2_kernel<<<eb, 256>>>(ei, att2);
    scatter2_kernel<<<eb, 256>>>(ei);
    bias2_kernel<<<(NN * OUTC + 255) / 256, 256>>>(bias2);

    // 5) decoder (gather-fused tensor-core GEMM + gelu)
    {
        dim3 grid(1, (ELL + 127) / 128);
        gemm_tc<1><<<grid, 256>>>(out2, eli, W_d1, nullptr, b_d1, nullptr,
                                  hbuf, nullptr, ELL, 2 * OUTC, HIDC);
    }
    dec_reduce<<<((ELL * 32) + 255) / 256, 256>>>(W_d2, b_d2, out);
}

// round 8
// speedup vs baseline: 1.7284x; 1.7284x over previous
#include <cuda_runtime.h>
#include <cuda_bf16.h>
#include <cstdint>
#include <cstddef>

#define NN   20000
#define EE   320000
#define ELL  100000
#define ET   (EE + NN)          // 340000 edges incl. self loops
#define INF_ 256
#define HIDC 128
#define OUTC 128
#define HH   4
#define C1   (HH * HIDC)        // 512

typedef __nv_bfloat16 bf16;

// ---------------- scratch (device globals: allocation-free) ----------------
__device__ float g_xl1[(size_t)NN * C1];
__device__ float g_xr1[(size_t)NN * C1];
__device__ float g_out1[(size_t)NN * C1];
__device__ float g_logits1[(size_t)ET * HH];
__device__ int   g_max1[NN * HH];
__device__ float g_sum1[NN * HH];
__device__ float g_xl2[(size_t)NN * OUTC];
__device__ float g_xr2[(size_t)NN * OUTC];
__device__ float g_out2[(size_t)NN * OUTC];
__device__ float g_logits2[ET];
__device__ int   g_max2[NN];
__device__ float g_sum2[NN];

// bf16 hi/lo splits of GEMM A operands
__device__ bf16 g_A1h[(size_t)NN * INF_];
__device__ bf16 g_A1l[(size_t)NN * INF_];
__device__ bf16 g_A2h[(size_t)NN * C1];
__device__ bf16 g_A2l[(size_t)NN * C1];
__device__ bf16 g_Z2h[(size_t)NN * OUTC];
__device__ bf16 g_Z2l[(size_t)NN * OUTC];

// transposed bf16 hi/lo weights [N][K]
__device__ bf16 g_BT1lh[C1 * INF_],  g_BT1ll[C1 * INF_];
__device__ bf16 g_BT1rh[C1 * INF_],  g_BT1rl[C1 * INF_];
__device__ bf16 g_BT2lh[OUTC * C1],  g_BT2ll[OUTC * C1];
__device__ bf16 g_BT2rh[OUTC * C1],  g_BT2rl[OUTC * C1];
__device__ bf16 g_BTdh[HIDC * 2 * OUTC], g_BTdl[HIDC * 2 * OUTC];

// ---------------- scalar helpers ----------------
__device__ __forceinline__ float lrelu(float x) { return x >= 0.f ? x : 0.2f * x; }

__device__ __forceinline__ float gelu_t(float x) {
    float x3 = x * x * x;
    return 0.5f * x * (1.f + tanhf(0.7978845608028654f * (x + 0.044715f * x3)));
}

__device__ __forceinline__ int fkey(float f) {
    int i = __float_as_int(f);
    return i >= 0 ? i : (i ^ 0x7fffffff);
}
__device__ __forceinline__ float keyf(int i) {
    return __int_as_float(i >= 0 ? i : (i ^ 0x7fffffff));
}

__device__ __forceinline__ void red_add_v4(float* p, float4 v) {
    asm volatile("red.global.add.v4.f32 [%0], {%1,%2,%3,%4};"
                 :: "l"(p), "f"(v.x), "f"(v.y), "f"(v.z), "f"(v.w) : "memory");
}

__device__ __forceinline__ void split_bf16(float v, bf16& h, bf16& l) {
    h = __float2bfloat16_rn(v);
    l = __float2bfloat16_rn(v - __bfloat162float(h));
}

// ---------------- PTX helpers ----------------
__device__ __forceinline__ uint32_t smem_u32(const void* p) {
    uint32_t a;
    asm("{ .reg .u64 t; cvta.to.shared.u64 t, %1; cvt.u32.u64 %0, t; }" : "=r"(a) : "l"(p));
    return a;
}

__device__ __forceinline__ void cpa16(uint32_t dst, const void* src, bool pred) {
    int sz = pred ? 16 : 0;
    asm volatile("cp.async.cg.shared.global [%0], [%1], 16, %2;\n"
                 :: "r"(dst), "l"(src), "r"(sz) : "memory");
}

__device__ __forceinline__ void ldm_x4(uint32_t r[4], uint32_t addr) {
    asm volatile("ldmatrix.sync.aligned.m8n8.x4.shared.b16 {%0,%1,%2,%3}, [%4];"
                 : "=r"(r[0]), "=r"(r[1]), "=r"(r[2]), "=r"(r[3]) : "r"(addr));
}

__device__ __forceinline__ void mma_bf16(float c[4], const uint32_t a[4],
                                         uint32_t b0, uint32_t b1) {
    asm volatile("mma.sync.aligned.m16n8k16.row.col.f32.bf16.bf16.f32 "
                 "{%0,%1,%2,%3}, {%4,%5,%6,%7}, {%8,%9}, {%0,%1,%2,%3};"
                 : "+f"(c[0]), "+f"(c[1]), "+f"(c[2]), "+f"(c[3])
                 : "r"(a[0]), "r"(a[1]), "r"(a[2]), "r"(a[3]), "r"(b0), "r"(b1));
}

// ---------------- init ----------------
__global__ void init_kernel() {
    int i = blockIdx.x * blockDim.x + threadIdx.x;
    if (i < NN * C1)   g_out1[i] = 0.f;
    if (i < NN * OUTC) g_out2[i] = 0.f;
    if (i < NN * HH) { g_max1[i] = (int)0x80000000; g_sum1[i] = 0.f; }
    if (i < NN)      { g_max2[i] = (int)0x80000000; g_sum2[i] = 0.f; }
}

// ---------------- prep: split x into bf16 hi/lo ----------------------------
__global__ void conv_x_kernel(const float* __restrict__ x) {
    int i = blockIdx.x * blockDim.x + threadIdx.x;
    if (i >= NN * INF_ / 4) return;
    float4 v = ((const float4*)x)[i];
    bf16 h0, l0, h1, l1, h2, l2, h3, l3;
    split_bf16(v.x, h0, l0); split_bf16(v.y, h1, l1);
    split_bf16(v.z, h2, l2); split_bf16(v.w, h3, l3);
    __nv_bfloat162* ph = (__nv_bfloat162*)(g_A1h + (size_t)i * 4);
    __nv_bfloat162* pl = (__nv_bfloat162*)(g_A1l + (size_t)i * 4);
    ph[0] = {h0, h1}; ph[1] = {h2, h3};
    pl[0] = {l0, l1}; pl[1] = {l2, l3};
}

// ---------------- prep: transpose + split weights  [K][N] -> [N][K] --------
__global__ void transpose_conv(const float* __restrict__ W_l1, const float* __restrict__ W_r1,
                               const float* __restrict__ W_l2, const float* __restrict__ W_r2,
                               const float* __restrict__ W_d1) {
    __shared__ float ts[32][33];
    const float* W; int Kz, Nz; bf16 *oh, *ol;
    switch (blockIdx.z) {
        case 0:  W = W_l1; Kz = INF_;     Nz = C1;   oh = g_BT1lh; ol = g_BT1ll; break;
        case 1:  W = W_r1; Kz = INF_;     Nz = C1;   oh = g_BT1rh; ol = g_BT1rl; break;
        case 2:  W = W_l2; Kz = C1;       Nz = OUTC; oh = g_BT2lh; ol = g_BT2ll; break;
        case 3:  W = W_r2; Kz = C1;       Nz = OUTC; oh = g_BT2rh; ol = g_BT2rl; break;
        default: W = W_d1; Kz = 2 * OUTC; Nz = HIDC; oh = g_BTdh;  ol = g_BTdl;  break;
    }
    int k0 = blockIdx.y * 32, n0 = blockIdx.x * 32;
    if (k0 >= Kz || n0 >= Nz) return;
    int tx = threadIdx.x, ty = threadIdx.y;
#pragma unroll
    for (int s = 0; s < 4; s++)
        ts[ty + s * 8][tx] = W[(size_t)(k0 + ty + s * 8) * Nz + n0 + tx];
    __syncthreads();
#pragma unroll
    for (int s = 0; s < 4; s++) {
        int n = n0 + ty + s * 8, k = k0 + tx;
        bf16 h, l;
        split_bf16(ts[tx][ty + s * 8], h, l);
        oh[(size_t)n * Kz + k] = h;
        ol[(size_t)n * Kz + k] = l;
    }
}

// ---------------- HMMA bf16x3 GEMM ------------------------------------------
// 128x128 CTA tile, BK=32, double-buffered cp.async, 8 warps of 64x32.
// MODE 0: dual-B  C{0,1} = A @ B{0,1}^T + bias{0,1}   (grid.x = 2*Nc/128)
// MODE 1: decoder C0[r]  = gelu(gather-A @ B0^T + bias0) . wd2 + bd2
#define LDH 40                    // smem row stride in halves (80B, conflict-free)
#define MATB (128 * LDH * 2)      // 10240 bytes per matrix
#define AOFF 1536
#define BOFF (AOFF + 4 * MATB)
#define SMTOT (BOFF + 4 * MATB)   // 83456 bytes

template<int MODE>
__global__ __launch_bounds__(256, 2) void gemm_mma(
    const bf16* __restrict__ Ah, const bf16* __restrict__ Al,
    const int* __restrict__ gidx,
    const bf16* __restrict__ B0h, const bf16* __restrict__ B0l,
    const bf16* __restrict__ B1h, const bf16* __restrict__ B1l,
    const float* __restrict__ bias0, const float* __restrict__ bias1,
    const float* __restrict__ wd2, const float* __restrict__ bd2,
    float* __restrict__ C0, float* __restrict__ C1p,
    int M, int K, int Nc)
{
    extern __shared__ char smem[];
    float* bias_s = (float*)smem;          // 128
    float* wd2_s  = bias_s + 128;          // 128
    float* red_s  = wd2_s + 128;           // 128
    uint32_t smb = smem_u32(smem);

    int tid = threadIdx.x, warp = tid >> 5, lane = tid & 31;
    int nb  = Nc >> 7;
    int mat = (blockIdx.x >= nb) ? 1 : 0;
    int bn  = (blockIdx.x - mat * nb) << 7;
    int bm  = (int)blockIdx.y << 7;

    const bf16* Bh = mat ? B1h : B0h;
    const bf16* Bl = mat ? B1l : B0l;
    const float* bias = mat ? bias1 : bias0;
    float* C = mat ? C1p : C0;

    if (tid < 128) {
        bias_s[tid] = bias[bn + tid];
        if (MODE == 1) { wd2_s[tid] = wd2[tid]; red_s[tid] = 0.f; }
    }

    // ---- loader setup: thread handles rows lrow, lrow+64 at koff (tid&3)*8
    int lrow = tid >> 2;
    int lko  = (tid & 3) << 3;             // halves
    bool aok[2];
    const bf16* gA[2][2];                  // MODE0: [rowhalf][hi/lo]
    const bf16* gN0[2][2];                 // MODE1 first node
    const bf16* gN1[2][2];                 // MODE1 second node
    const bf16* gB[2][2];
#pragma unroll
    for (int rh = 0; rh < 2; rh++) {
        int r = bm + lrow + rh * 64;
        aok[rh] = r < M;
        int rc = aok[rh] ? r : (M - 1);
        if (MODE == 0) {
            gA[rh][0] = Ah + (size_t)rc * K;
            gA[rh][1] = Al + (size_t)rc * K;
        } else {
            int n0 = gidx[rc], n1 = gidx[ELL + rc];
            gN0[rh][0] = Ah + (size_t)n0 * OUTC;
            gN0[rh][1] = Al + (size_t)n0 * OUTC;
            gN1[rh][0] = Ah + (size_t)n1 * OUTC;
            gN1[rh][1] = Al + (size_t)n1 * OUTC;
        }
        int br = bn + lrow + rh * 64;
        gB[rh][0] = Bh + (size_t)br * K;
        gB[rh][1] = Bl + (size_t)br * K;
    }

    auto load_stage = [&](int st, int c) {
        int k0h = c << 5;
#pragma unroll
        for (int rh = 0; rh < 2; rh++) {
            int row = lrow + rh * 64;
            uint32_t soff = (uint32_t)(row * LDH + lko) * 2;
#pragma unroll
            for (int h = 0; h < 2; h++) {
                const bf16* srcA;
                if (MODE == 0) srcA = gA[rh][h] + k0h + lko;
                else {
                    int kg = k0h + lko;
                    srcA = (kg < OUTC) ? (gN0[rh][h] + kg) : (gN1[rh][h] + kg - OUTC);
                }
                cpa16(smb + AOFF + (uint32_t)(st * 2 + h) * MATB + soff, srcA, aok[rh]);
                cpa16(smb + BOFF + (uint32_t)(st * 2 + h) * MATB + soff,
                      gB[rh][h] + k0h + lko, true);
            }
        }
        asm volatile("cp.async.commit_group;" ::: "memory");
    };

    // ---- fragment addressing
    int wm = (warp >> 2) << 6;             // 0 / 64
    int wn = (warp & 3) << 5;              // 0..96
    int lr16 = lane & 15;
    int lh8  = (lane >> 4) << 3;           // halves

    float acc[4][4][4];
#pragma unroll
    for (int i = 0; i < 4; i++)
#pragma unroll
        for (int j = 0; j < 4; j++)
#pragma unroll
            for (int q = 0; q < 4; q++) acc[i][j][q] = 0.f;

    int nch = K >> 5;
    load_stage(0, 0);
    if (nch > 1) load_stage(1, 1);

    for (int c = 0; c < nch; c++) {
        if (c + 1 < nch) asm volatile("cp.async.wait_group 1;" ::: "memory");
        else             asm volatile("cp.async.wait_group 0;" ::: "memory");
        __syncthreads();

        int st = c & 1;
        uint32_t aBh = smb + AOFF + (uint32_t)(st * 2 + 0) * MATB;
        uint32_t aBl = smb + AOFF + (uint32_t)(st * 2 + 1) * MATB;
        uint32_t bBh = smb + BOFF + (uint32_t)(st * 2 + 0) * MATB;
        uint32_t bBl = smb + BOFF + (uint32_t)(st * 2 + 1) * MATB;

#pragma unroll
        for (int ks = 0; ks < 2; ks++) {
            int kin = ks * 16 + lh8;
            uint32_t b_h[2][4], b_l[2][4];
#pragma unroll
            for (int np = 0; np < 2; np++) {
                uint32_t off = (uint32_t)((wn + np * 16 + lr16) * LDH + kin) * 2;
                ldm_x4(b_h[np], bBh + off);
                ldm_x4(b_l[np], bBl + off);
            }
#pragma unroll
            for (int mf = 0; mf < 4; mf++) {
                uint32_t a_h[4], a_l[4];
                uint32_t off = (uint32_t)((wm + mf * 16 + lr16) * LDH + kin) * 2;
                ldm_x4(a_h, aBh + off);
                ldm_x4(a_l, aBl + off);
#pragma unroll
                for (int nf = 0; nf < 4; nf++) {
                    int np = nf >> 1, s = nf & 1;
                    uint32_t bh0 = b_h[np][s], bh1 = b_h[np][2 + s];
                    uint32_t bl0 = b_l[np][s], bl1 = b_l[np][2 + s];
                    mma_bf16(acc[mf][nf], a_h, bh0, bh1);
                    mma_bf16(acc[mf][nf], a_l, bh0, bh1);
                    mma_bf16(acc[mf][nf], a_h, bl0, bl1);
                }
            }
        }
        __syncthreads();
        if (c + 2 < nch) load_stage((c + 2) & 1, c + 2);
    }

    // ---- epilogue
    int grp = lane >> 2, t4 = lane & 3;
    if (MODE == 0) {
#pragma unroll
        for (int mf = 0; mf < 4; mf++) {
            int r0 = bm + wm + mf * 16 + grp;
#pragma unroll
            for (int nf = 0; nf < 4; nf++) {
                int colL = wn + nf * 8 + t4 * 2;
                float b0 = bias_s[colL], b1 = bias_s[colL + 1];
                if (r0 < M)
                    *(float2*)(C + (size_t)r0 * Nc + bn + colL) =
                        make_float2(acc[mf][nf][0] + b0, acc[mf][nf][1] + b1);
                if (r0 + 8 < M)
                    *(float2*)(C + (size_t)(r0 + 8) * Nc + bn + colL) =
                        make_float2(acc[mf][nf][2] + b0, acc[mf][nf][3] + b1);
            }
        }
    } else {
#pragma unroll
        for (int mf = 0; mf < 4; mf++) {
            float s0 = 0.f, s1 = 0.f;
#pragma unroll
            for (int nf = 0; nf < 4; nf++) {
                int colL = wn + nf * 8 + t4 * 2;
                float b0 = bias_s[colL], b1 = bias_s[colL + 1];
                float w0 = wd2_s[colL], w1 = wd2_s[colL + 1];
                s0 += gelu_t(acc[mf][nf][0] + b0) * w0 + gelu_t(acc[mf][nf][1] + b1) * w1;
                s1 += gelu_t(acc[mf][nf][2] + b0) * w0 + gelu_t(acc[mf][nf][3] + b1) * w1;
            }
            s0 += __shfl_xor_sync(0xffffffffu, s0, 1);
            s0 += __shfl_xor_sync(0xffffffffu, s0, 2);
            s1 += __shfl_xor_sync(0xffffffffu, s1, 1);
            s1 += __shfl_xor_sync(0xffffffffu, s1, 2);
            if (t4 == 0) {
                atomicAdd(&red_s[wm + mf * 16 + grp], s0);
                atomicAdd(&red_s[wm + mf * 16 + grp + 8], s1);
            }
        }
        __syncthreads();
        if (tid < 128) {
            int r = bm + tid;
            if (r < M) C[r] = red_s[tid] + bd2[0];
        }
    }
}

// ---------------- layer 1 edge kernels (H=4, C=128) ------------------------
__global__ __launch_bounds__(256) void logits1_kernel(const int* __restrict__ ei,
                                                      const float* __restrict__ att)
{
    int gw = (blockIdx.x * blockDim.x + threadIdx.x) >> 5;
    if (gw >= ET) return;
    int lane = threadIdx.x & 31;
    int src, dst;
    if (gw < EE) { src = ei[gw]; dst = ei[EE + gw]; }
    else         { src = dst = gw - EE; }

    const float4* pl = (const float4*)(g_xl1 + (size_t)src * C1);
    const float4* pr = (const float4*)(g_xr1 + (size_t)dst * C1);
    const float4* pa = (const float4*)att;

    float res[HH];
#pragma unroll
    for (int h = 0; h < HH; h++) {
        int f = h * 32 + lane;
        float4 l = pl[f], r = pr[f], a = pa[f];
        float p = lrelu(l.x + r.x) * a.x + lrelu(l.y + r.y) * a.y +
                  lrelu(l.z + r.z) * a.z + lrelu(l.w + r.w) * a.w;
        p += __shfl_down_sync(0xffffffffu, p, 16);
        p += __shfl_down_sync(0xffffffffu, p, 8);
        p += __shfl_down_sync(0xffffffffu, p, 4);
        p += __shfl_down_sync(0xffffffffu, p, 2);
        p += __shfl_down_sync(0xffffffffu, p, 1);
        res[h] = p;
    }
    if (lane == 0) {
#pragma unroll
        for (int h = 0; h < HH; h++) {
            g_logits1[(size_t)gw * HH + h] = res[h];
            atomicMax(&g_max1[dst * HH + h], fkey(res[h]));
        }
    }
}

__global__ __launch_bounds__(256) void scatter1_kernel(const int* __restrict__ ei)
{
    int gw = (blockIdx.x * blockDim.x + threadIdx.x) >> 5;
    if (gw >= ET) return;
    int lane = threadIdx.x & 31;
    int src, dst;
    if (gw < EE) { src = ei[gw]; dst = ei[EE + gw]; }
    else         { src = dst = gw - EE; }

    const float4* pl = (const float4*)(g_xl1 + (size_t)src * C1);
    float* pd = g_out1 + (size_t)dst * C1;
    float a[HH];
#pragma unroll
    for (int h = 0; h < HH; h++) {
        a[h] = __expf(g_logits1[(size_t)gw * HH + h] - keyf(g_max1[dst * HH + h]));
        if (lane == 0) atomicAdd(&g_sum1[dst * HH + h], a[h]);
    }
#pragma unroll
    for (int h = 0; h < HH; h++) {
        int f = h * 32 + lane;
        float4 v = pl[f];
        v.x *= a[h]; v.y *= a[h]; v.z *= a[h]; v.w *= a[h];
        red_add_v4(pd + f * 4, v);
    }
}

// normalize + bias + gelu, then split into bf16 hi/lo for GEMM2
__global__ __launch_bounds__(256) void gelu1_kernel(const float* __restrict__ bias1)
{
    int i = blockIdx.x * blockDim.x + threadIdx.x;
    if (i >= NN * C1 / 4) return;
    int i4 = i * 4;
    int n = i4 >> 9, h = (i4 >> 7) & 3;
    float s = g_sum1[(n << 2) + h];
    float4 v = *(const float4*)(g_out1 + i4);
    float4 b = *(const float4*)(bias1 + (i4 & (C1 - 1)));
    float o0 = gelu_t(v.x / s + b.x), o1 = gelu_t(v.y / s + b.y);
    float o2 = gelu_t(v.z / s + b.z), o3 = gelu_t(v.w / s + b.w);
    bf16 h0, l0, h1, l1, h2, l2, h3, l3;
    split_bf16(o0, h0, l0); split_bf16(o1, h1, l1);
    split_bf16(o2, h2, l2); split_bf16(o3, h3, l3);
    __nv_bfloat162* ph = (__nv_bfloat162*)(g_A2h + (size_t)i4);
    __nv_bfloat162* pl = (__nv_bfloat162*)(g_A2l + (size_t)i4);
    ph[0] = {h0, h1}; ph[1] = {h2, h3};
    pl[0] = {l0, l1}; pl[1] = {l2, l3};
}

// ---------------- layer 2 edge kernels (H=1, C=128) ------------------------
__global__ __launch_bounds__(256) void logits2_kernel(const int* __restrict__ ei,
                                                      const float* __restrict__ att2)
{
    int gw = (blockIdx.x * blockDim.x + threadIdx.x) >> 5;
    if (gw >= ET) return;
    int lane = threadIdx.x & 31;
    int src, dst;
    if (gw < EE) { src = ei[gw]; dst = ei[EE + gw]; }
    else         { src = dst = gw - EE; }

    const float4* pl = (const float4*)(g_xl2 + (size_t)src * OUTC);
    const float4* pr = (const float4*)(g_xr2 + (size_t)dst * OUTC);
    float4 l = pl[lane], r = pr[lane], a = ((const float4*)att2)[lane];
    float p = lrelu(l.x + r.x) * a.x + lrelu(l.y + r.y) * a.y +
              lrelu(l.z + r.z) * a.z + lrelu(l.w + r.w) * a.w;
    p += __shfl_down_sync(0xffffffffu, p, 16);
    p += __shfl_down_sync(0xffffffffu, p, 8);
    p += __shfl_down_sync(0xffffffffu, p, 4);
    p += __shfl_down_sync(0xffffffffu, p, 2);
    p += __shfl_down_sync(0xffffffffu, p, 1);
    if (lane == 0) {
        g_logits2[gw] = p;
        atomicMax(&g_max2[dst], fkey(p));
    }
}

__global__ __launch_bounds__(256) void scatter2_kernel(const int* __restrict__ ei)
{
    int gw = (blockIdx.x * blockDim.x + threadIdx.x) >> 5;
    if (gw >= ET) return;
    int lane = threadIdx.x & 31;
    int src, dst;
    if (gw < EE) { src = ei[gw]; dst = ei[EE + gw]; }
    else         { src = dst = gw - EE; }

    float a = __expf(g_logits2[gw] - keyf(g_max2[dst]));
    if (lane == 0) atomicAdd(&g_sum2[dst], a);
    const float4* pl = (const float4*)(g_xl2 + (size_t)src * OUTC);
    float4 v = pl[lane];
    v.x *= a; v.y *= a; v.z *= a; v.w *= a;
    red_add_v4(g_out2 + (size_t)dst * OUTC + lane * 4, v);
}

// normalize + bias, split z2 into bf16 hi/lo for decoder GEMM
__global__ __launch_bounds__(256) void bias2_kernel(const float* __restrict__ bias2)
{
    int i = blockIdx.x * blockDim.x + threadIdx.x;
    if (i >= NN * OUTC / 4) return;
    int i4 = i * 4;
    float s = g_sum2[i4 >> 7];
    float4 v = *(const float4*)(g_out2 + i4);
    float4 b = *(const float4*)(bias2 + (i4 & (OUTC - 1)));
    float o0 = v.x / s + b.x, o1 = v.y / s + b.y;
    float o2 = v.z / s + b.z, o3 = v.w / s + b.w;
    bf16 h0, l0, h1, l1, h2, l2, h3, l3;
    split_bf16(o0, h0, l0); split_bf16(o1, h1, l1);
    split_bf16(o2, h2, l2); split_bf16(o3, h3, l3);
    __nv_bfloat162* ph = (__nv_bfloat162*)(g_Z2h + (size_t)i4);
    __nv_bfloat162* pl = (__nv_bfloat162*)(g_Z2l + (size_t)i4);
    ph[0] = {h0, h1}; ph[1] = {h2, h3};
    pl[0] = {l0, l1}; pl[1] = {l2, l3};
}

// ---------------- launch ----------------------------------------------------
extern "C" void kernel_launch(void* const* d_in, const int* in_sizes, int n_in,
                              void* d_out, int out_size)
{
    const float* x     = (const float*)d_in[0];
    const int*   ei    = (const int*)d_in[1];
    const int*   eli   = (const int*)d_in[2];
    const float* W_l1  = (const float*)d_in[3];
    const float* b_l1  = (const float*)d_in[4];
    const float* W_r1  = (const float*)d_in[5];
    const float* b_r1  = (const float*)d_in[6];
    const float* att1  = (const float*)d_in[7];
    const float* bias1 = (const float*)d_in[8];
    const float* W_l2  = (const float*)d_in[9];
    const float* b_l2  = (const float*)d_in[10];
    const float* W_r2  = (const float*)d_in[11];
    const float* b_r2  = (const float*)d_in[12];
    const float* att2  = (const float*)d_in[13];
    const float* bias2 = (const float*)d_in[14];
    const float* W_d1  = (const float*)d_in[15];
    const float* b_d1  = (const float*)d_in[16];
    const float* W_d2  = (const float*)d_in[17];
    const float* b_d2  = (const float*)d_in[18];
    float* out = (float*)d_out;

    cudaFuncSetAttribute(gemm_mma<0>, cudaFuncAttributeMaxDynamicSharedMemorySize, SMTOT);
    cudaFuncSetAttribute(gemm_mma<1>, cudaFuncAttributeMaxDynamicSharedMemorySize, SMTOT);

    float *xl1, *xr1, *xl2, *xr2;
    bf16 *a1h, *a1l, *a2h, *a2l, *z2h, *z2l;
    bf16 *bt1lh, *bt1ll, *bt1rh, *bt1rl, *bt2lh, *bt2ll, *bt2rh, *bt2rl, *btdh, *btdl;
    cudaGetSymbolAddress((void**)&xl1,  g_xl1);
    cudaGetSymbolAddress((void**)&xr1,  g_xr1);
    cudaGetSymbolAddress((void**)&xl2,  g_xl2);
    cudaGetSymbolAddress((void**)&xr2,  g_xr2);
    cudaGetSymbolAddress((void**)&a1h,  g_A1h);
    cudaGetSymbolAddress((void**)&a1l,  g_A1l);
    cudaGetSymbolAddress((void**)&a2h,  g_A2h);
    cudaGetSymbolAddress((void**)&a2l,  g_A2l);
    cudaGetSymbolAddress((void**)&z2h,  g_Z2h);
    cudaGetSymbolAddress((void**)&z2l,  g_Z2l);
    cudaGetSymbolAddress((void**)&bt1lh, g_BT1lh);
    cudaGetSymbolAddress((void**)&bt1ll, g_BT1ll);
    cudaGetSymbolAddress((void**)&bt1rh, g_BT1rh);
    cudaGetSymbolAddress((void**)&bt1rl, g_BT1rl);
    cudaGetSymbolAddress((void**)&bt2lh, g_BT2lh);
    cudaGetSymbolAddress((void**)&bt2ll, g_BT2ll);
    cudaGetSymbolAddress((void**)&bt2rh, g_BT2rh);
    cudaGetSymbolAddress((void**)&bt2rl, g_BT2rl);
    cudaGetSymbolAddress((void**)&btdh,  g_BTdh);
    cudaGetSymbolAddress((void**)&btdl,  g_BTdl);

    // 0) reset accumulators + prep operands
    init_kernel<<<(NN * C1 + 255) / 256, 256>>>();
    conv_x_kernel<<<(NN * INF_ / 4 + 255) / 256, 256>>>(x);
    {
        dim3 grid(16, 16, 5), blk(32, 8);
        transpose_conv<<<grid, blk>>>(W_l1, W_r1, W_l2, W_r2, W_d1);
    }

    // 1) layer-1 transforms: xl1 = x@W_l1+b_l1, xr1 = x@W_r1+b_r1
    {
        dim3 grid(2 * (C1 / 128), (NN + 127) / 128);
        gemm_mma<0><<<grid, 256, SMTOT>>>(a1h, a1l, nullptr,
                                          bt1lh, bt1ll, bt1rh, bt1rl,
                                          b_l1, b_r1, nullptr, nullptr,
                                          xl1, xr1, NN, INF_, C1);
    }

    // 2) layer-1 attention
    int eb = ((ET * 32) + 255) / 256;
    logits1_kernel<<<eb, 256>>>(ei, att1);
    scatter1_kernel<<<eb, 256>>>(ei);
    gelu1_kernel<<<(NN * C1 / 4 + 255) / 256, 256>>>(bias1);

    // 3) layer-2 transforms
    {
        dim3 grid(2 * (OUTC / 128), (NN + 127) / 128);
        gemm_mma<0><<<grid, 256, SMTOT>>>(a2h, a2l, nullptr,
                                          bt2lh, bt2ll, bt2rh, bt2rl,
                                          b_l2, b_r2, nullptr, nullptr,
                                          xl2, xr2, NN, C1, OUTC);
    }

    // 4) layer-2 attention
    logits2_kernel<<<eb, 256>>>(ei, att2);
    scatter2_kernel<<<eb, 256>>>(ei);
    bias2_kernel<<<(NN * OUTC / 4 + 255) / 256, 256>>>(bias2);

    // 5) decoder (gather-fused GEMM + gelu + final dot, single kernel)
    {
        dim3 grid(1, (ELL + 127) / 128);
        gemm_mma<1><<<grid, 256, SMTOT>>>(z2h, z2l, eli,
                                          btdh, btdl, nullptr, nullptr,
                                          b_d1, nullptr, W_d2, b_d2,
                                          out, nullptr, ELL, 2 * OUTC, HIDC);
    }
}

// round 11
// speedup vs baseline: 2.1511x; 1.2446x over previous
#include <cuda_runtime.h>
#include <cuda_bf16.h>
#include <cstdint>
#include <cstddef>

#define NN   20000
#define EE   320000
#define ELL  100000
#define INF_ 256
#define HIDC 128
#define OUTC 128
#define HH   4
#define C1   (HH * HIDC)        // 512

typedef __nv_bfloat16 bf16;

// ---------------- scratch (device globals: allocation-free) ----------------
__device__ float g_xl1[(size_t)NN * C1];
__device__ float g_xr1[(size_t)NN * C1];
__device__ float g_xl2[(size_t)NN * OUTC];
__device__ float g_xr2[(size_t)NN * OUTC];

// CSR by destination (self-loops handled analytically, not stored)
__device__ int g_deg[NN + 1];
__device__ int g_rowptr[NN + 1];
__device__ int g_cursor[NN];
__device__ int g_csr[EE];

// bf16 hi/lo splits of GEMM A operands
__device__ bf16 g_A1h[(size_t)NN * INF_];
__device__ bf16 g_A1l[(size_t)NN * INF_];
__device__ bf16 g_A2h[(size_t)NN * C1];
__device__ bf16 g_A2l[(size_t)NN * C1];
__device__ bf16 g_Z2h[(size_t)NN * OUTC];
__device__ bf16 g_Z2l[(size_t)NN * OUTC];

// transposed bf16 hi/lo weights [N][K]
__device__ bf16 g_BT1lh[C1 * INF_],  g_BT1ll[C1 * INF_];
__device__ bf16 g_BT1rh[C1 * INF_],  g_BT1rl[C1 * INF_];
__device__ bf16 g_BT2lh[OUTC * C1],  g_BT2ll[OUTC * C1];
__device__ bf16 g_BT2rh[OUTC * C1],  g_BT2rl[OUTC * C1];
__device__ bf16 g_BTdh[HIDC * 2 * OUTC], g_BTdl[HIDC * 2 * OUTC];

// ---------------- scalar helpers ----------------
__device__ __forceinline__ float lrelu(float x) { return x >= 0.f ? x : 0.2f * x; }

__device__ __forceinline__ float gelu_t(float x) {
    float x3 = x * x * x;
    return 0.5f * x * (1.f + tanhf(0.7978845608028654f * (x + 0.044715f * x3)));
}

__device__ __forceinline__ void split_bf16(float v, bf16& h, bf16& l) {
    h = __float2bfloat16_rn(v);
    l = __float2bfloat16_rn(v - __bfloat162float(h));
}

// ---------------- PTX helpers ----------------
__device__ __forceinline__ uint32_t smem_u32(const void* p) {
    uint32_t a;
    asm("{ .reg .u64 t; cvta.to.shared.u64 t, %1; cvt.u32.u64 %0, t; }" : "=r"(a) : "l"(p));
    return a;
}

__device__ __forceinline__ void cpa16(uint32_t dst, const void* src, bool pred) {
    int sz = pred ? 16 : 0;
    asm volatile("cp.async.cg.shared.global [%0], [%1], 16, %2;\n"
                 :: "r"(dst), "l"(src), "r"(sz) : "memory");
}

__device__ __forceinline__ void ldm_x4(uint32_t r[4], uint32_t addr) {
    asm volatile("ldmatrix.sync.aligned.m8n8.x4.shared.b16 {%0,%1,%2,%3}, [%4];"
                 : "=r"(r[0]), "=r"(r[1]), "=r"(r[2]), "=r"(r[3]) : "r"(addr));
}

__device__ __forceinline__ void mma_bf16(float c[4], const uint32_t a[4],
                                         uint32_t b0, uint32_t b1) {
    asm volatile("mma.sync.aligned.m16n8k16.row.col.f32.bf16.bf16.f32 "
                 "{%0,%1,%2,%3}, {%4,%5,%6,%7}, {%8,%9}, {%0,%1,%2,%3};"
                 : "+f"(c[0]), "+f"(c[1]), "+f"(c[2]), "+f"(c[3])
                 : "r"(a[0]), "r"(a[1]), "r"(a[2]), "r"(a[3]), "r"(b0), "r"(b1));
}

// ---------------- CSR construction -----------------------------------------
__global__ void csr_zero() {
    int i = blockIdx.x * blockDim.x + threadIdx.x;
    if (i <= NN) g_deg[i] = 0;
}

__global__ void csr_hist(const int* __restrict__ ei) {
    int i = blockIdx.x * blockDim.x + threadIdx.x;
    if (i < EE) atomicAdd(&g_deg[ei[EE + i]], 1);
}

// single-block exclusive scan over NN degree counts -> rowptr + cursor
__global__ __launch_bounds__(1024) void csr_scan() {
    __shared__ int part[1024];
    const int CH = 20;                 // 1024*20 = 20480 >= NN
    int t = threadIdx.x;
    int base = t * CH;
    int local[CH];
    int s = 0;
#pragma unroll
    for (int i = 0; i < CH; i++) {
        int idx = base + i;
        int v = (idx < NN) ? g_deg[idx] : 0;
        local[i] = s;
        s += v;
    }
    part[t] = s;
    __syncthreads();
    for (int d = 1; d < 1024; d <<= 1) {
        int v = (t >= d) ? part[t - d] : 0;
        __syncthreads();
        part[t] += v;
        __syncthreads();
    }
    int off = (t > 0) ? part[t - 1] : 0;
#pragma unroll
    for (int i = 0; i < CH; i++) {
        int idx = base + i;
        if (idx < NN) {
            int r = off + local[i];
            g_rowptr[idx] = r;
            g_cursor[idx] = r;
        }
    }
    if (t == 1023) g_rowptr[NN] = part[1023];
}

__global__ void csr_fill(const int* __restrict__ ei) {
    int i = blockIdx.x * blockDim.x + threadIdx.x;
    if (i >= EE) return;
    int d = ei[EE + i];
    int pos = atomicAdd(&g_cursor[d], 1);
    g_csr[pos] = ei[i];
}

// ---------------- prep: split x into bf16 hi/lo ----------------------------
__global__ void conv_x_kernel(const float* __restrict__ x) {
    int i = blockIdx.x * blockDim.x + threadIdx.x;
    if (i >= NN * INF_ / 4) return;
    float4 v = ((const float4*)x)[i];
    bf16 h0, l0, h1, l1, h2, l2, h3, l3;
    split_bf16(v.x, h0, l0); split_bf16(v.y, h1, l1);
    split_bf16(v.z, h2, l2); split_bf16(v.w, h3, l3);
    __nv_bfloat162* ph = (__nv_bfloat162*)(g_A1h + (size_t)i * 4);
    __nv_bfloat162* pl = (__nv_bfloat162*)(g_A1l + (size_t)i * 4);
    ph[0] = {h0, h1}; ph[1] = {h2, h3};
    pl[0] = {l0, l1}; pl[1] = {l2, l3};
}

// ---------------- prep: transpose + split weights  [K][N] -> [N][K] --------
__global__ void transpose_conv(const float* __restrict__ W_l1, const float* __restrict__ W_r1,
                               const float* __restrict__ W_l2, const float* __restrict__ W_r2,
                               const float* __restrict__ W_d1) {
    __shared__ float ts[32][33];
    const float* W; int Kz, Nz; bf16 *oh, *ol;
    switch (blockIdx.z) {
        case 0:  W = W_l1; Kz = INF_;     Nz = C1;   oh = g_BT1lh; ol = g_BT1ll; break;
        case 1:  W = W_r1; Kz = INF_;     Nz = C1;   oh = g_BT1rh; ol = g_BT1rl; break;
        case 2:  W = W_l2; Kz = C1;       Nz = OUTC; oh = g_BT2lh; ol = g_BT2ll; break;
        case 3:  W = W_r2; Kz = C1;       Nz = OUTC; oh = g_BT2rh; ol = g_BT2rl; break;
        default: W = W_d1; Kz = 2 * OUTC; Nz = HIDC; oh = g_BTdh;  ol = g_BTdl;  break;
    }
    int k0 = blockIdx.y * 32, n0 = blockIdx.x * 32;
    if (k0 >= Kz || n0 >= Nz) return;
    int tx = threadIdx.x, ty = threadIdx.y;
#pragma unroll
    for (int s = 0; s < 4; s++)
        ts[ty + s * 8][tx] = W[(size_t)(k0 + ty + s * 8) * Nz + n0 + tx];
    __syncthreads();
#pragma unroll
    for (int s = 0; s < 4; s++) {
        int n = n0 + ty + s * 8, k = k0 + tx;
        bf16 h, l;
        split_bf16(ts[tx][ty + s * 8], h, l);
        oh[(size_t)n * Kz + k] = h;
        ol[(size_t)n * Kz + k] = l;
    }
}

// ---------------- HMMA bf16x3 GEMM (unchanged from R8) ----------------------
#define LDH 40
#define MATB (128 * LDH * 2)
#define AOFF 1536
#define BOFF (AOFF + 4 * MATB)
#define SMTOT (BOFF + 4 * MATB)

template<int MODE>
__global__ __launch_bounds__(256, 2) void gemm_mma(
    const bf16* __restrict__ Ah, const bf16* __restrict__ Al,
    const int* __restrict__ gidx,
    const bf16* __restrict__ B0h, const bf16* __restrict__ B0l,
    const bf16* __restrict__ B1h, const bf16* __restrict__ B1l,
    const float* __restrict__ bias0, const float* __restrict__ bias1,
    const float* __restrict__ wd2, const float* __restrict__ bd2,
    float* __restrict__ C0, float* __restrict__ C1p,
    int M, int K, int Nc)
{
    extern __shared__ char smem[];
    float* bias_s = (float*)smem;
    float* wd2_s  = bias_s + 128;
    float* red_s  = wd2_s + 128;
    uint32_t smb = smem_u32(smem);

    int tid = threadIdx.x, warp = tid >> 5, lane = tid & 31;
    int nb  = Nc >> 7;
    int mat = (blockIdx.x >= nb) ? 1 : 0;
    int bn  = (blockIdx.x - mat * nb) << 7;
    int bm  = (int)blockIdx.y << 7;

    const bf16* Bh = mat ? B1h : B0h;
    const bf16* Bl = mat ? B1l : B0l;
    const float* bias = mat ? bias1 : bias0;
    float* C = mat ? C1p : C0;

    if (tid < 128) {
        bias_s[tid] = bias[bn + tid];
        if (MODE == 1) { wd2_s[tid] = wd2[tid]; red_s[tid] = 0.f; }
    }

    int lrow = tid >> 2;
    int lko  = (tid & 3) << 3;
    bool aok[2];
    const bf16* gA[2][2];
    const bf16* gN0[2][2];
    const bf16* gN1[2][2];
    const bf16* gB[2][2];
#pragma unroll
    for (int rh = 0; rh < 2; rh++) {
        int r = bm + lrow + rh * 64;
        aok[rh] = r < M;
        int rc = aok[rh] ? r : (M - 1);
        if (MODE == 0) {
            gA[rh][0] = Ah + (size_t)rc * K;
            gA[rh][1] = Al + (size_t)rc * K;
        } else {
            int n0 = gidx[rc], n1 = gidx[ELL + rc];
            gN0[rh][0] = Ah + (size_t)n0 * OUTC;
            gN0[rh][1] = Al + (size_t)n0 * OUTC;
            gN1[rh][0] = Ah + (size_t)n1 * OUTC;
            gN1[rh][1] = Al + (size_t)n1 * OUTC;
        }
        int br = bn + lrow + rh * 64;
        gB[rh][0] = Bh + (size_t)br * K;
        gB[rh][1] = Bl + (size_t)br * K;
    }

    auto load_stage = [&](int st, int c) {
        int k0h = c << 5;
#pragma unroll
        for (int rh = 0; rh < 2; rh++) {
            int row = lrow + rh * 64;
            uint32_t soff = (uint32_t)(row * LDH + lko) * 2;
#pragma unroll
            for (int h = 0; h < 2; h++) {
                const bf16* srcA;
                if (MODE == 0) srcA = gA[rh][h] + k0h + lko;
                else {
                    int kg = k0h + lko;
                    srcA = (kg < OUTC) ? (gN0[rh][h] + kg) : (gN1[rh][h] + kg - OUTC);
                }
                cpa16(smb + AOFF + (uint32_t)(st * 2 + h) * MATB + soff, srcA, aok[rh]);
                cpa16(smb + BOFF + (uint32_t)(st * 2 + h) * MATB + soff,
                      gB[rh][h] + k0h + lko, true);
            }
        }
        asm volatile("cp.async.commit_group;" ::: "memory");
    };

    int wm = (warp >> 2) << 6;
    int wn = (warp & 3) << 5;
    int lr16 = lane & 15;
    int lh8  = (lane >> 4) << 3;

    float acc[4][4][4];
#pragma unroll
    for (int i = 0; i < 4; i++)
#pragma unroll
        for (int j = 0; j < 4; j++)
#pragma unroll
            for (int q = 0; q < 4; q++) acc[i][j][q] = 0.f;

    int nch = K >> 5;
    load_stage(0, 0);
    if (nch > 1) load_stage(1, 1);

    for (int c = 0; c < nch; c++) {
        if (c + 1 < nch) asm volatile("cp.async.wait_group 1;" ::: "memory");
        else             asm volatile("cp.async.wait_group 0;" ::: "memory");
        __syncthreads();

        int st = c & 1;
        uint32_t aBh = smb + AOFF + (uint32_t)(st * 2 + 0) * MATB;
        uint32_t aBl = smb + AOFF + (uint32_t)(st * 2 + 1) * MATB;
        uint32_t bBh = smb + BOFF + (uint32_t)(st * 2 + 0) * MATB;
        uint32_t bBl = smb + BOFF + (uint32_t)(st * 2 + 1) * MATB;

#pragma unroll
        for (int ks = 0; ks < 2; ks++) {
            int kin = ks * 16 + lh8;
            uint32_t b_h[2][4], b_l[2][4];
#pragma unroll
            for (int np = 0; np < 2; np++) {
                uint32_t off = (uint32_t)((wn + np * 16 + lr16) * LDH + kin) * 2;
                ldm_x4(b_h[np], bBh + off);
                ldm_x4(b_l[np], bBl + off);
            }
#pragma unroll
            for (int mf = 0; mf < 4; mf++) {
                uint32_t a_h[4], a_l[4];
                uint32_t off = (uint32_t)((wm + mf * 16 + lr16) * LDH + kin) * 2;
                ldm_x4(a_h, aBh + off);
                ldm_x4(a_l, aBl + off);
#pragma unroll
                for (int nf = 0; nf < 4; nf++) {
                    int np = nf >> 1, s = nf & 1;
                    uint32_t bh0 = b_h[np][s], bh1 = b_h[np][2 + s];
                    uint32_t bl0 = b_l[np][s], bl1 = b_l[np][2 + s];
                    mma_bf16(acc[mf][nf], a_h, bh0, bh1);
                    mma_bf16(acc[mf][nf], a_l, bh0, bh1);
                    mma_bf16(acc[mf][nf], a_h, bl0, bl1);
                }
            }
        }
        __syncthreads();
        if (c + 2 < nch) load_stage((c + 2) & 1, c + 2);
    }

    int grp = lane >> 2, t4 = lane & 3;
    if (MODE == 0) {
#pragma unroll
        for (int mf = 0; mf < 4; mf++) {
            int r0 = bm + wm + mf * 16 + grp;
#pragma unroll
            for (int nf = 0; nf < 4; nf++) {
                int colL = wn + nf * 8 + t4 * 2;
                float b0 = bias_s[colL], b1 = bias_s[colL + 1];
                if (r0 < M)
                    *(float2*)(C + (size_t)r0 * Nc + bn + colL) =
                        make_float2(acc[mf][nf][0] + b0, acc[mf][nf][1] + b1);
                if (r0 + 8 < M)
                    *(float2*)(C + (size_t)(r0 + 8) * Nc + bn + colL) =
                        make_float2(acc[mf][nf][2] + b0, acc[mf][nf][3] + b1);
            }
        }
    } else {
#pragma unroll
        for (int mf = 0; mf < 4; mf++) {
            float s0 = 0.f, s1 = 0.f;
#pragma unroll
            for (int nf = 0; nf < 4; nf++) {
                int colL = wn + nf * 8 + t4 * 2;
                float b0 = bias_s[colL], b1 = bias_s[colL + 1];
                float w0 = wd2_s[colL], w1 = wd2_s[colL + 1];
                s0 += gelu_t(acc[mf][nf][0] + b0) * w0 + gelu_t(acc[mf][nf][1] + b1) * w1;
                s1 += gelu_t(acc[mf][nf][2] + b0) * w0 + gelu_t(acc[mf][nf][3] + b1) * w1;
            }
            s0 += __shfl_xor_sync(0xffffffffu, s0, 1);
            s0 += __shfl_xor_sync(0xffffffffu, s0, 2);
            s1 += __shfl_xor_sync(0xffffffffu, s1, 1);
            s1 += __shfl_xor_sync(0xffffffffu, s1, 2);
            if (t4 == 0) {
                atomicAdd(&red_s[wm + mf * 16 + grp], s0);
                atomicAdd(&red_s[wm + mf * 16 + grp + 8], s1);
            }
        }
        __syncthreads();
        if (tid < 128) {
            int r = bm + tid;
            if (r < M) C[r] = red_s[tid] + bd2[0];
        }
    }
}

// ---------------- fused GATv2 edge phase, layer 1 ---------------------------
// One warp per (node, head). Two passes over CSR neighbors:
// pass A: exact max of logits; pass B: recompute logit, accumulate exp-weighted
// messages + denominator in registers. Epilogue: /sum + bias + gelu + bf16 split.
__global__ __launch_bounds__(256) void gat1_node(const float* __restrict__ att,
                                                 const float* __restrict__ bias1)
{
    int w = (blockIdx.x * blockDim.x + threadIdx.x) >> 5;
    if (w >= NN * HH) return;
    int n = w >> 2, h = w & 3;
    int lane = threadIdx.x & 31;
    int off = h * HIDC + lane * 4;

    float4 xr = *(const float4*)(g_xr1 + (size_t)n * C1 + off);
    float4 at = *(const float4*)(att + off);
    float4 vs = *(const float4*)(g_xl1 + (size_t)n * C1 + off);

    int beg = g_rowptr[n], end = g_rowptr[n + 1];

    auto logit4 = [&](float4 v) -> float {
        float p = lrelu(v.x + xr.x) * at.x + lrelu(v.y + xr.y) * at.y +
                  lrelu(v.z + xr.z) * at.z + lrelu(v.w + xr.w) * at.w;
        p += __shfl_xor_sync(0xffffffffu, p, 16);
        p += __shfl_xor_sync(0xffffffffu, p, 8);
        p += __shfl_xor_sync(0xffffffffu, p, 4);
        p += __shfl_xor_sync(0xffffffffu, p, 2);
        p += __shfl_xor_sync(0xffffffffu, p, 1);
        return p;
    };

    float lself = logit4(vs);
    float m = lself;
#pragma unroll 4
    for (int j = beg; j < end; j++) {
        int s = __ldg(&g_csr[j]);
        float4 v = *(const float4*)(g_xl1 + (size_t)s * C1 + off);
        m = fmaxf(m, logit4(v));
    }

    float e0 = __expf(lself - m);
    float sum = e0;
    float4 acc = make_float4(e0 * vs.x, e0 * vs.y, e0 * vs.z, e0 * vs.w);
#pragma unroll 4
    for (int j = beg; j < end; j++) {
        int s = __ldg(&g_csr[j]);
        float4 v = *(const float4*)(g_xl1 + (size_t)s * C1 + off);
        float e = __expf(logit4(v) - m);
        sum += e;
        acc.x += e * v.x; acc.y += e * v.y; acc.z += e * v.z; acc.w += e * v.w;
    }

    float4 b = *(const float4*)(bias1 + off);
    float o0 = gelu_t(acc.x / sum + b.x);
    float o1 = gelu_t(acc.y / sum + b.y);
    float o2 = gelu_t(acc.z / sum + b.z);
    float o3 = gelu_t(acc.w / sum + b.w);
    bf16 h0, l0, h1, l1, h2, l2, h3, l3;
    split_bf16(o0, h0, l0); split_bf16(o1, h1, l1);
    split_bf16(o2, h2, l2); split_bf16(o3, h3, l3);
    __nv_bfloat162* ph = (__nv_bfloat162*)(g_A2h + (size_t)n * C1 + off);
    __nv_bfloat162* pl = (__nv_bfloat162*)(g_A2l + (size_t)n * C1 + off);
    ph[0] = {h0, h1}; ph[1] = {h2, h3};
    pl[0] = {l0, l1}; pl[1] = {l2, l3};
}

// ---------------- fused GATv2 edge phase, layer 2 (H=1) ---------------------
__global__ __launch_bounds__(256) void gat2_node(const float* __restrict__ att2,
                                                 const float* __restrict__ bias2)
{
    int n = (blockIdx.x * blockDim.x + threadIdx.x) >> 5;
    if (n >= NN) return;
    int lane = threadIdx.x & 31;
    int off = lane * 4;

    float4 xr = *(const float4*)(g_xr2 + (size_t)n * OUTC + off);
    float4 at = *(const float4*)(att2 + off);
    float4 vs = *(const float4*)(g_xl2 + (size_t)n * OUTC + off);

    int beg = g_rowptr[n], end = g_rowptr[n + 1];

    auto logit4 = [&](float4 v) -> float {
        float p = lrelu(v.x + xr.x) * at.x + lrelu(v.y + xr.y) * at.y +
                  lrelu(v.z + xr.z) * at.z + lrelu(v.w + xr.w) * at.w;
        p += __shfl_xor_sync(0xffffffffu, p, 16);
        p += __shfl_xor_sync(0xffffffffu, p, 8);
        p += __shfl_xor_sync(0xffffffffu, p, 4);
        p += __shfl_xor_sync(0xffffffffu, p, 2);
        p += __shfl_xor_sync(0xffffffffu, p, 1);
        return p;
    };

    float lself = logit4(vs);
    float m = lself;
#pragma unroll 4
    for (int j = beg; j < end; j++) {
        int s = __ldg(&g_csr[j]);
        float4 v = *(const float4*)(g_xl2 + (size_t)s * OUTC + off);
        m = fmaxf(m, logit4(v));
    }

    float e0 = __expf(lself - m);
    float sum = e0;
    float4 acc = make_float4(e0 * vs.x, e0 * vs.y, e0 * vs.z, e0 * vs.w);
#pragma unroll 4
    for (int j = beg; j < end; j++) {
        int s = __ldg(&g_csr[j]);
        float4 v = *(const float4*)(g_xl2 + (size_t)s * OUTC + off);
        float e = __expf(logit4(v) - m);
        sum += e;
        acc.x += e * v.x; acc.y += e * v.y; acc.z += e * v.z; acc.w += e * v.w;
    }

    float4 b = *(const float4*)(bias2 + off);
    float o0 = acc.x / sum + b.x;
    float o1 = acc.y / sum + b.y;
    float o2 = acc.z / sum + b.z;
    float o3 = acc.w / sum + b.w;
    bf16 h0, l0, h1, l1, h2, l2, h3, l3;
    split_bf16(o0, h0, l0); split_bf16(o1, h1, l1);
    split_bf16(o2, h2, l2); split_bf16(o3, h3, l3);
    __nv_bfloat162* ph = (__nv_bfloat162*)(g_Z2h + (size_t)n * OUTC + off);
    __nv_bfloat162* pl = (__nv_bfloat162*)(g_Z2l + (size_t)n * OUTC + off);
    ph[0] = {h0, h1}; ph[1] = {h2, h3};
    pl[0] = {l0, l1}; pl[1] = {l2, l3};
}

// ---------------- launch ----------------------------------------------------
extern "C" void kernel_launch(void* const* d_in, const int* in_sizes, int n_in,
                              void* d_out, int out_size)
{
    const float* x     = (const float*)d_in[0];
    const int*   ei    = (const int*)d_in[1];
    const int*   eli   = (const int*)d_in[2];
    const float* W_l1  = (const float*)d_in[3];
    const float* b_l1  = (const float*)d_in[4];
    const float* W_r1  = (const float*)d_in[5];
    const float* b_r1  = (const float*)d_in[6];
    const float* att1  = (const float*)d_in[7];
    const float* bias1 = (const float*)d_in[8];
    const float* W_l2  = (const float*)d_in[9];
    const float* b_l2  = (const float*)d_in[10];
    const float* W_r2  = (const float*)d_in[11];
    const float* b_r2  = (const float*)d_in[12];
    const float* att2  = (const float*)d_in[13];
    const float* bias2 = (const float*)d_in[14];
    const float* W_d1  = (const float*)d_in[15];
    const float* b_d1  = (const float*)d_in[16];
    const float* W_d2  = (const float*)d_in[17];
    const float* b_d2  = (const float*)d_in[18];
    float* out = (float*)d_out;

    cudaFuncSetAttribute(gemm_mma<0>, cudaFuncAttributeMaxDynamicSharedMemorySize, SMTOT);
    cudaFuncSetAttribute(gemm_mma<1>, cudaFuncAttributeMaxDynamicSharedMemorySize, SMTOT);

    float *xl1, *xr1, *xl2, *xr2;
    bf16 *a1h, *a1l, *a2h, *a2l, *z2h, *z2l;
    bf16 *bt1lh, *bt1ll, *bt1rh, *bt1rl, *bt2lh, *bt2ll, *bt2rh, *bt2rl, *btdh, *btdl;
    cudaGetSymbolAddress((void**)&xl1,  g_xl1);
    cudaGetSymbolAddress((void**)&xr1,  g_xr1);
    cudaGetSymbolAddress((void**)&xl2,  g_xl2);
    cudaGetSymbolAddress((void**)&xr2,  g_xr2);
    cudaGetSymbolAddress((void**)&a1h,  g_A1h);
    cudaGetSymbolAddress((void**)&a1l,  g_A1l);
    cudaGetSymbolAddress((void**)&a2h,  g_A2h);
    cudaGetSymbolAddress((void**)&a2l,  g_A2l);
    cudaGetSymbolAddress((void**)&z2h,  g_Z2h);
    cudaGetSymbolAddress((void**)&z2l,  g_Z2l);
    cudaGetSymbolAddress((void**)&bt1lh, g_BT1lh);
    cudaGetSymbolAddress((void**)&bt1ll, g_BT1ll);
    cudaGetSymbolAddress((void**)&bt1rh, g_BT1rh);
    cudaGetSymbolAddress((void**)&bt1rl, g_BT1rl);
    cudaGetSymbolAddress((void**)&bt2lh, g_BT2lh);
    cudaGetSymbolAddress((void**)&bt2ll, g_BT2ll);
    cudaGetSymbolAddress((void**)&bt2rh, g_BT2rh);
    cudaGetSymbolAddress((void**)&bt2rl, g_BT2rl);
    cudaGetSymbolAddress((void**)&btdh,  g_BTdh);
    cudaGetSymbolAddress((void**)&btdl,  g_BTdl);

    // 0) CSR build + operand prep
    csr_zero<<<(NN + 1 + 255) / 256, 256>>>();
    csr_hist<<<(EE + 255) / 256, 256>>>(ei);
    csr_scan<<<1, 1024>>>();
    csr_fill<<<(EE + 255) / 256, 256>>>(ei);
    conv_x_kernel<<<(NN * INF_ / 4 + 255) / 256, 256>>>(x);
    {
        dim3 grid(16, 16, 5), blk(32, 8);
        transpose_conv<<<grid, blk>>>(W_l1, W_r1, W_l2, W_r2, W_d1);
    }

    // 1) layer-1 transforms: xl1 = x@W_l1+b_l1, xr1 = x@W_r1+b_r1
    {
        dim3 grid(2 * (C1 / 128), (NN + 127) / 128);
        gemm_mma<0><<<grid, 256, SMTOT>>>(a1h, a1l, nullptr,
                                          bt1lh, bt1ll, bt1rh, bt1rl,
                                          b_l1, b_r1, nullptr, nullptr,
                                          xl1, xr1, NN, INF_, C1);
    }

    // 2) layer-1 fused attention (logits + softmax + aggregate + gelu + split)
    gat1_node<<<(NN * HH * 32 + 255) / 256, 256>>>(att1, bias1);

    // 3) layer-2 transforms
    {
        dim3 grid(2 * (OUTC / 128), (NN + 127) / 128);
        gemm_mma<0><<<grid, 256, SMTOT>>>(a2h, a2l, nullptr,
                                          bt2lh, bt2ll, bt2rh, bt2rl,
                                          b_l2, b_r2, nullptr, nullptr,
                                          xl2, xr2, NN, C1, OUTC);
    }

    // 4) layer-2 fused attention
    gat2_node<<<(NN * 32 + 255) / 256, 256>>>(att2, bias2);

    // 5) decoder (gather-fused GEMM + gelu + final dot, single kernel)
    {
        dim3 grid(1, (ELL + 127) / 128);
        gemm_mma<1><<<grid, 256, SMTOT>>>(z2h, z2l, eli,
                                          btdh, btdl, nullptr, nullptr,
                                          b_d1, nullptr, W_d2, b_d2,
                                          out, nullptr, ELL, 2 * OUTC, HIDC);
    }
}

// round 12
// speedup vs baseline: 2.3957x; 1.1137x over previous
#include <cuda_runtime.h>
#include <cuda_bf16.h>
#include <cstdint>
#include <cstddef>

#define NN   20000
#define EE   320000
#define ELL  100000
#define INF_ 256
#define HIDC 128
#define OUTC 128
#define HH   4
#define C1   (HH * HIDC)        // 512

typedef __nv_bfloat16 bf16;

// ---------------- scratch (device globals: allocation-free) ----------------
__device__ float g_xl1[(size_t)NN * C1];
__device__ float g_xr1[(size_t)NN * C1];
__device__ float g_xl2[(size_t)NN * OUTC];
__device__ float g_xr2[(size_t)NN * OUTC];

// CSR by destination (self-loops handled analytically, not stored)
__device__ int g_deg[NN + 1];
__device__ int g_rowptr[NN + 1];
__device__ int g_cursor[NN];
__device__ int g_csr[EE];

// bf16 hi/lo splits of GEMM A operands
__device__ bf16 g_A1h[(size_t)NN * INF_];
__device__ bf16 g_A1l[(size_t)NN * INF_];
__device__ bf16 g_A2h[(size_t)NN * C1];
__device__ bf16 g_A2l[(size_t)NN * C1];
__device__ bf16 g_Z2h[(size_t)NN * OUTC];
__device__ bf16 g_Z2l[(size_t)NN * OUTC];

// transposed bf16 hi/lo weights [N][K]
__device__ bf16 g_BT1lh[C1 * INF_],  g_BT1ll[C1 * INF_];
__device__ bf16 g_BT1rh[C1 * INF_],  g_BT1rl[C1 * INF_];
__device__ bf16 g_BT2lh[OUTC * C1],  g_BT2ll[OUTC * C1];
__device__ bf16 g_BT2rh[OUTC * C1],  g_BT2rl[OUTC * C1];
__device__ bf16 g_BTdh[HIDC * 2 * OUTC], g_BTdl[HIDC * 2 * OUTC];

// ---------------- scalar helpers ----------------
__device__ __forceinline__ float lrelu(float x) { return x >= 0.f ? x : 0.2f * x; }

__device__ __forceinline__ float gelu_t(float x) {
    float x3 = x * x * x;
    return 0.5f * x * (1.f + tanhf(0.7978845608028654f * (x + 0.044715f * x3)));
}

__device__ __forceinline__ void split_bf16(float v, bf16& h, bf16& l) {
    h = __float2bfloat16_rn(v);
    l = __float2bfloat16_rn(v - __bfloat162float(h));
}

// ---------------- PTX helpers ----------------
__device__ __forceinline__ uint32_t smem_u32(const void* p) {
    uint32_t a;
    asm("{ .reg .u64 t; cvta.to.shared.u64 t, %1; cvt.u32.u64 %0, t; }" : "=r"(a) : "l"(p));
    return a;
}

__device__ __forceinline__ void cpa16(uint32_t dst, const void* src, bool pred) {
    int sz = pred ? 16 : 0;
    asm volatile("cp.async.cg.shared.global [%0], [%1], 16, %2;\n"
                 :: "r"(dst), "l"(src), "r"(sz) : "memory");
}

__device__ __forceinline__ void ldm_x4(uint32_t r[4], uint32_t addr) {
    asm volatile("ldmatrix.sync.aligned.m8n8.x4.shared.b16 {%0,%1,%2,%3}, [%4];"
                 : "=r"(r[0]), "=r"(r[1]), "=r"(r[2]), "=r"(r[3]) : "r"(addr));
}

__device__ __forceinline__ void mma_bf16(float c[4], const uint32_t a[4],
                                         uint32_t b0, uint32_t b1) {
    asm volatile("mma.sync.aligned.m16n8k16.row.col.f32.bf16.bf16.f32 "
                 "{%0,%1,%2,%3}, {%4,%5,%6,%7}, {%8,%9}, {%0,%1,%2,%3};"
                 : "+f"(c[0]), "+f"(c[1]), "+f"(c[2]), "+f"(c[3])
                 : "r"(a[0]), "r"(a[1]), "r"(a[2]), "r"(a[3]), "r"(b0), "r"(b1));
}

// ---------------- CSR construction -----------------------------------------
__global__ void csr_zero() {
    int i = blockIdx.x * blockDim.x + threadIdx.x;
    if (i <= NN) g_deg[i] = 0;
}

__global__ void csr_hist(const int* __restrict__ ei) {
    int i = blockIdx.x * blockDim.x + threadIdx.x;
    if (i < EE) atomicAdd(&g_deg[ei[EE + i]], 1);
}

// single-block exclusive scan over NN degree counts -> rowptr + cursor
__global__ __launch_bounds__(1024) void csr_scan() {
    __shared__ int part[1024];
    const int CH = 20;                 // 1024*20 = 20480 >= NN
    int t = threadIdx.x;
    int base = t * CH;
    int local[CH];
    int s = 0;
#pragma unroll
    for (int i = 0; i < CH; i++) {
        int idx = base + i;
        int v = (idx < NN) ? g_deg[idx] : 0;
        local[i] = s;
        s += v;
    }
    part[t] = s;
    __syncthreads();
    for (int d = 1; d < 1024; d <<= 1) {
        int v = (t >= d) ? part[t - d] : 0;
        __syncthreads();
        part[t] += v;
        __syncthreads();
    }
    int off = (t > 0) ? part[t - 1] : 0;
#pragma unroll
    for (int i = 0; i < CH; i++) {
        int idx = base + i;
        if (idx < NN) {
            int r = off + local[i];
            g_rowptr[idx] = r;
            g_cursor[idx] = r;
        }
    }
    if (t == 1023) g_rowptr[NN] = part[1023];
}

__global__ void csr_fill(const int* __restrict__ ei) {
    int i = blockIdx.x * blockDim.x + threadIdx.x;
    if (i >= EE) return;
    int d = ei[EE + i];
    int pos = atomicAdd(&g_cursor[d], 1);
    g_csr[pos] = ei[i];
}

// ---------------- prep: split x into bf16 hi/lo ----------------------------
__global__ void conv_x_kernel(const float* __restrict__ x) {
    int i = blockIdx.x * blockDim.x + threadIdx.x;
    if (i >= NN * INF_ / 4) return;
    float4 v = ((const float4*)x)[i];
    bf16 h0, l0, h1, l1, h2, l2, h3, l3;
    split_bf16(v.x, h0, l0); split_bf16(v.y, h1, l1);
    split_bf16(v.z, h2, l2); split_bf16(v.w, h3, l3);
    __nv_bfloat162* ph = (__nv_bfloat162*)(g_A1h + (size_t)i * 4);
    __nv_bfloat162* pl = (__nv_bfloat162*)(g_A1l + (size_t)i * 4);
    ph[0] = {h0, h1}; ph[1] = {h2, h3};
    pl[0] = {l0, l1}; pl[1] = {l2, l3};
}

// ---------------- prep: transpose + split weights  [K][N] -> [N][K] --------
__global__ void transpose_conv(const float* __restrict__ W_l1, const float* __restrict__ W_r1,
                               const float* __restrict__ W_l2, const float* __restrict__ W_r2,
                               const float* __restrict__ W_d1) {
    __shared__ float ts[32][33];
    const float* W; int Kz, Nz; bf16 *oh, *ol;
    switch (blockIdx.z) {
        case 0:  W = W_l1; Kz = INF_;     Nz = C1;   oh = g_BT1lh; ol = g_BT1ll; break;
        case 1:  W = W_r1; Kz = INF_;     Nz = C1;   oh = g_BT1rh; ol = g_BT1rl; break;
        case 2:  W = W_l2; Kz = C1;       Nz = OUTC; oh = g_BT2lh; ol = g_BT2ll; break;
        case 3:  W = W_r2; Kz = C1;       Nz = OUTC; oh = g_BT2rh; ol = g_BT2rl; break;
        default: W = W_d1; Kz = 2 * OUTC; Nz = HIDC; oh = g_BTdh;  ol = g_BTdl;  break;
    }
    int k0 = blockIdx.y * 32, n0 = blockIdx.x * 32;
    if (k0 >= Kz || n0 >= Nz) return;
    int tx = threadIdx.x, ty = threadIdx.y;
#pragma unroll
    for (int s = 0; s < 4; s++)
        ts[ty + s * 8][tx] = W[(size_t)(k0 + ty + s * 8) * Nz + n0 + tx];
    __syncthreads();
#pragma unroll
    for (int s = 0; s < 4; s++) {
        int n = n0 + ty + s * 8, k = k0 + tx;
        bf16 h, l;
        split_bf16(ts[tx][ty + s * 8], h, l);
        oh[(size_t)n * Kz + k] = h;
        ol[(size_t)n * Kz + k] = l;
    }
}

// ---------------- HMMA bf16x3 GEMM (unchanged from R8) ----------------------
#define LDH 40
#define MATB (128 * LDH * 2)
#define AOFF 1536
#define BOFF (AOFF + 4 * MATB)
#define SMTOT (BOFF + 4 * MATB)

template<int MODE>
__global__ __launch_bounds__(256, 2) void gemm_mma(
    const bf16* __restrict__ Ah, const bf16* __restrict__ Al,
    const int* __restrict__ gidx,
    const bf16* __restrict__ B0h, const bf16* __restrict__ B0l,
    const bf16* __restrict__ B1h, const bf16* __restrict__ B1l,
    const float* __restrict__ bias0, const float* __restrict__ bias1,
    const float* __restrict__ wd2, const float* __restrict__ bd2,
    float* __restrict__ C0, float* __restrict__ C1p,
    int M, int K, int Nc)
{
    extern __shared__ char smem[];
    float* bias_s = (float*)smem;
    float* wd2_s  = bias_s + 128;
    float* red_s  = wd2_s + 128;
    uint32_t smb = smem_u32(smem);

    int tid = threadIdx.x, warp = tid >> 5, lane = tid & 31;
    int nb  = Nc >> 7;
    int mat = (blockIdx.x >= nb) ? 1 : 0;
    int bn  = (blockIdx.x - mat * nb) << 7;
    int bm  = (int)blockIdx.y << 7;

    const bf16* Bh = mat ? B1h : B0h;
    const bf16* Bl = mat ? B1l : B0l;
    const float* bias = mat ? bias1 : bias0;
    float* C = mat ? C1p : C0;

    if (tid < 128) {
        bias_s[tid] = bias[bn + tid];
        if (MODE == 1) { wd2_s[tid] = wd2[tid]; red_s[tid] = 0.f; }
    }

    int lrow = tid >> 2;
    int lko  = (tid & 3) << 3;
    bool aok[2];
    const bf16* gA[2][2];
    const bf16* gN0[2][2];
    const bf16* gN1[2][2];
    const bf16* gB[2][2];
#pragma unroll
    for (int rh = 0; rh < 2; rh++) {
        int r = bm + lrow + rh * 64;
        aok[rh] = r < M;
        int rc = aok[rh] ? r : (M - 1);
        if (MODE == 0) {
            gA[rh][0] = Ah + (size_t)rc * K;
            gA[rh][1] = Al + (size_t)rc * K;
        } else {
            int n0 = gidx[rc], n1 = gidx[ELL + rc];
            gN0[rh][0] = Ah + (size_t)n0 * OUTC;
            gN0[rh][1] = Al + (size_t)n0 * OUTC;
            gN1[rh][0] = Ah + (size_t)n1 * OUTC;
            gN1[rh][1] = Al + (size_t)n1 * OUTC;
        }
        int br = bn + lrow + rh * 64;
        gB[rh][0] = Bh + (size_t)br * K;
        gB[rh][1] = Bl + (size_t)br * K;
    }

    auto load_stage = [&](int st, int c) {
        int k0h = c << 5;
#pragma unroll
        for (int rh = 0; rh < 2; rh++) {
            int row = lrow + rh * 64;
            uint32_t soff = (uint32_t)(row * LDH + lko) * 2;
#pragma unroll
            for (int h = 0; h < 2; h++) {
                const bf16* srcA;
                if (MODE == 0) srcA = gA[rh][h] + k0h + lko;
                else {
                    int kg = k0h + lko;
                    srcA = (kg < OUTC) ? (gN0[rh][h] + kg) : (gN1[rh][h] + kg - OUTC);
                }
                cpa16(smb + AOFF + (uint32_t)(st * 2 + h) * MATB + soff, srcA, aok[rh]);
                cpa16(smb + BOFF + (uint32_t)(st * 2 + h) * MATB + soff,
                      gB[rh][h] + k0h + lko, true);
            }
        }
        asm volatile("cp.async.commit_group;" ::: "memory");
    };

    int wm = (warp >> 2) << 6;
    int wn = (warp & 3) << 5;
    int lr16 = lane & 15;
    int lh8  = (lane >> 4) << 3;

    float acc[4][4][4];
#pragma unroll
    for (int i = 0; i < 4; i++)
#pragma unroll
        for (int j = 0; j < 4; j++)
#pragma unroll
            for (int q = 0; q < 4; q++) acc[i][j][q] = 0.f;

    int nch = K >> 5;
    load_stage(0, 0);
    if (nch > 1) load_stage(1, 1);

    for (int c = 0; c < nch; c++) {
        if (c + 1 < nch) asm volatile("cp.async.wait_group 1;" ::: "memory");
        else             asm volatile("cp.async.wait_group 0;" ::: "memory");
        __syncthreads();

        int st = c & 1;
        uint32_t aBh = smb + AOFF + (uint32_t)(st * 2 + 0) * MATB;
        uint32_t aBl = smb + AOFF + (uint32_t)(st * 2 + 1) * MATB;
        uint32_t bBh = smb + BOFF + (uint32_t)(st * 2 + 0) * MATB;
        uint32_t bBl = smb + BOFF + (uint32_t)(st * 2 + 1) * MATB;

#pragma unroll
        for (int ks = 0; ks < 2; ks++) {
            int kin = ks * 16 + lh8;
            uint32_t b_h[2][4], b_l[2][4];
#pragma unroll
            for (int np = 0; np < 2; np++) {
                uint32_t off = (uint32_t)((wn + np * 16 + lr16) * LDH + kin) * 2;
                ldm_x4(b_h[np], bBh + off);
                ldm_x4(b_l[np], bBl + off);
            }
#pragma unroll
            for (int mf = 0; mf < 4; mf++) {
                uint32_t a_h[4], a_l[4];
                uint32_t off = (uint32_t)((wm + mf * 16 + lr16) * LDH + kin) * 2;
                ldm_x4(a_h, aBh + off);
                ldm_x4(a_l, aBl + off);
#pragma unroll
                for (int nf = 0; nf < 4; nf++) {
                    int np = nf >> 1, s = nf & 1;
                    uint32_t bh0 = b_h[np][s], bh1 = b_h[np][2 + s];
                    uint32_t bl0 = b_l[np][s], bl1 = b_l[np][2 + s];
                    mma_bf16(acc[mf][nf], a_h, bh0, bh1);
                    mma_bf16(acc[mf][nf], a_l, bh0, bh1);
                    mma_bf16(acc[mf][nf], a_h, bl0, bl1);
                }
            }
        }
        __syncthreads();
        if (c + 2 < nch) load_stage((c + 2) & 1, c + 2);
    }

    int grp = lane >> 2, t4 = lane & 3;
    if (MODE == 0) {
#pragma unroll
        for (int mf = 0; mf < 4; mf++) {
            int r0 = bm + wm + mf * 16 + grp;
#pragma unroll
            for (int nf = 0; nf < 4; nf++) {
                int colL = wn + nf * 8 + t4 * 2;
                float b0 = bias_s[colL], b1 = bias_s[colL + 1];
                if (r0 < M)
                    *(float2*)(C + (size_t)r0 * Nc + bn + colL) =
                        make_float2(acc[mf][nf][0] + b0, acc[mf][nf][1] + b1);
                if (r0 + 8 < M)
                    *(float2*)(C + (size_t)(r0 + 8) * Nc + bn + colL) =
                        make_float2(acc[mf][nf][2] + b0, acc[mf][nf][3] + b1);
            }
        }
    } else {
#pragma unroll
        for (int mf = 0; mf < 4; mf++) {
            float s0 = 0.f, s1 = 0.f;
#pragma unroll
            for (int nf = 0; nf < 4; nf++) {
                int colL = wn + nf * 8 + t4 * 2;
                float b0 = bias_s[colL], b1 = bias_s[colL + 1];
                float w0 = wd2_s[colL], w1 = wd2_s[colL + 1];
                s0 += gelu_t(acc[mf][nf][0] + b0) * w0 + gelu_t(acc[mf][nf][1] + b1) * w1;
                s1 += gelu_t(acc[mf][nf][2] + b0) * w0 + gelu_t(acc[mf][nf][3] + b1) * w1;
            }
            s0 += __shfl_xor_sync(0xffffffffu, s0, 1);
            s0 += __shfl_xor_sync(0xffffffffu, s0, 2);
            s1 += __shfl_xor_sync(0xffffffffu, s1, 1);
            s1 += __shfl_xor_sync(0xffffffffu, s1, 2);
            if (t4 == 0) {
                atomicAdd(&red_s[wm + mf * 16 + grp], s0);
                atomicAdd(&red_s[wm + mf * 16 + grp + 8], s1);
            }
        }
        __syncthreads();
        if (tid < 128) {
            int r = bm + tid;
            if (r < M) C[r] = red_s[tid] + bd2[0];
        }
    }
}

// ---------------- fused GATv2 edge phase, layer 1 (online softmax) ----------
// One warp per (node, head). SINGLE pass over CSR neighbors with running
// max/sum/acc rescaling. Epilogue: /sum + bias + gelu + bf16 split.
__global__ __launch_bounds__(256) void gat1_node(const float* __restrict__ att,
                                                 const float* __restrict__ bias1)
{
    int w = (blockIdx.x * blockDim.x + threadIdx.x) >> 5;
    if (w >= NN * HH) return;
    int n = w >> 2, h = w & 3;
    int lane = threadIdx.x & 31;
    int off = h * HIDC + lane * 4;

    float4 xr = *(const float4*)(g_xr1 + (size_t)n * C1 + off);
    float4 at = *(const float4*)(att + off);
    float4 vs = *(const float4*)(g_xl1 + (size_t)n * C1 + off);

    int beg = g_rowptr[n], end = g_rowptr[n + 1];

    auto logit4 = [&](float4 v) -> float {
        float p = lrelu(v.x + xr.x) * at.x + lrelu(v.y + xr.y) * at.y +
                  lrelu(v.z + xr.z) * at.z + lrelu(v.w + xr.w) * at.w;
        p += __shfl_xor_sync(0xffffffffu, p, 16);
        p += __shfl_xor_sync(0xffffffffu, p, 8);
        p += __shfl_xor_sync(0xffffffffu, p, 4);
        p += __shfl_xor_sync(0xffffffffu, p, 2);
        p += __shfl_xor_sync(0xffffffffu, p, 1);
        return p;
    };

    // init with self-loop (logit lself, message vs)
    float m = logit4(vs);
    float sum = 1.f;
    float4 acc = vs;

#pragma unroll 2
    for (int j = beg; j < end; j++) {
        int s = __ldg(&g_csr[j]);
        float4 v = *(const float4*)(g_xl1 + (size_t)s * C1 + off);
        float l = logit4(v);
        float nm = fmaxf(m, l);
        float sc = __expf(m - nm);
        float e  = __expf(l - nm);
        sum = sum * sc + e;
        acc.x = acc.x * sc + e * v.x;
        acc.y = acc.y * sc + e * v.y;
        acc.z = acc.z * sc + e * v.z;
        acc.w = acc.w * sc + e * v.w;
        m = nm;
    }

    float4 b = *(const float4*)(bias1 + off);
    float o0 = gelu_t(acc.x / sum + b.x);
    float o1 = gelu_t(acc.y / sum + b.y);
    float o2 = gelu_t(acc.z / sum + b.z);
    float o3 = gelu_t(acc.w / sum + b.w);
    bf16 h0, l0, h1, l1, h2, l2, h3, l3;
    split_bf16(o0, h0, l0); split_bf16(o1, h1, l1);
    split_bf16(o2, h2, l2); split_bf16(o3, h3, l3);
    __nv_bfloat162* ph = (__nv_bfloat162*)(g_A2h + (size_t)n * C1 + off);
    __nv_bfloat162* pl = (__nv_bfloat162*)(g_A2l + (size_t)n * C1 + off);
    ph[0] = {h0, h1}; ph[1] = {h2, h3};
    pl[0] = {l0, l1}; pl[1] = {l2, l3};
}

// ---------------- fused GATv2 edge phase, layer 2 (H=1, online softmax) -----
__global__ __launch_bounds__(256) void gat2_node(const float* __restrict__ att2,
                                                 const float* __restrict__ bias2)
{
    int n = (blockIdx.x * blockDim.x + threadIdx.x) >> 5;
    if (n >= NN) return;
    int lane = threadIdx.x & 31;
    int off = lane * 4;

    float4 xr = *(const float4*)(g_xr2 + (size_t)n * OUTC + off);
    float4 at = *(const float4*)(att2 + off);
    float4 vs = *(const float4*)(g_xl2 + (size_t)n * OUTC + off);

    int beg = g_rowptr[n], end = g_rowptr[n + 1];

    auto logit4 = [&](float4 v) -> float {
        float p = lrelu(v.x + xr.x) * at.x + lrelu(v.y + xr.y) * at.y +
                  lrelu(v.z + xr.z) * at.z + lrelu(v.w + xr.w) * at.w;
        p += __shfl_xor_sync(0xffffffffu, p, 16);
        p += __shfl_xor_sync(0xffffffffu, p, 8);
        p += __shfl_xor_sync(0xffffffffu, p, 4);
        p += __shfl_xor_sync(0xffffffffu, p, 2);
        p += __shfl_xor_sync(0xffffffffu, p, 1);
        return p;
    };

    float m = logit4(vs);
    float sum = 1.f;
    float4 acc = vs;

#pragma unroll 2
    for (int j = beg; j < end; j++) {
        int s = __ldg(&g_csr[j]);
        float4 v = *(const float4*)(g_xl2 + (size_t)s * OUTC + off);
        float l = logit4(v);
        float nm = fmaxf(m, l);
        float sc = __expf(m - nm);
        float e  = __expf(l - nm);
        sum = sum * sc + e;
        acc.x = acc.x * sc + e * v.x;
        acc.y = acc.y * sc + e * v.y;
        acc.z = acc.z * sc + e * v.z;
        acc.w = acc.w * sc + e * v.w;
        m = nm;
    }

    float4 b = *(const float4*)(bias2 + off);
    float o0 = acc.x / sum + b.x;
    float o1 = acc.y / sum + b.y;
    float o2 = acc.z / sum + b.z;
    float o3 = acc.w / sum + b.w;
    bf16 h0, l0, h1, l1, h2, l2, h3, l3;
    split_bf16(o0, h0, l0); split_bf16(o1, h1, l1);
    split_bf16(o2, h2, l2); split_bf16(o3, h3, l3);
    __nv_bfloat162* ph = (__nv_bfloat162*)(g_Z2h + (size_t)n * OUTC + off);
    __nv_bfloat162* pl = (__nv_bfloat162*)(g_Z2l + (size_t)n * OUTC + off);
    ph[0] = {h0, h1}; ph[1] = {h2, h3};
    pl[0] = {l0, l1}; pl[1] = {l2, l3};
}

// ---------------- launch ----------------------------------------------------
extern "C" void kernel_launch(void* const* d_in, const int* in_sizes, int n_in,
                              void* d_out, int out_size)
{
    const float* x     = (const float*)d_in[0];
    const int*   ei    = (const int*)d_in[1];
    const int*   eli   = (const int*)d_in[2];
    const float* W_l1  = (const float*)d_in[3];
    const float* b_l1  = (const float*)d_in[4];
    const float* W_r1  = (const float*)d_in[5];
    const float* b_r1  = (const float*)d_in[6];
    const float* att1  = (const float*)d_in[7];
    const float* bias1 = (const float*)d_in[8];
    const float* W_l2  = (const float*)d_in[9];
    const float* b_l2  = (const float*)d_in[10];
    const float* W_r2  = (const float*)d_in[11];
    const float* b_r2  = (const float*)d_in[12];
    const float* att2  = (const float*)d_in[13];
    const float* bias2 = (const float*)d_in[14];
    const float* W_d1  = (const float*)d_in[15];
    const float* b_d1  = (const float*)d_in[16];
    const float* W_d2  = (const float*)d_in[17];
    const float* b_d2  = (const float*)d_in[18];
    float* out = (float*)d_out;

    cudaFuncSetAttribute(gemm_mma<0>, cudaFuncAttributeMaxDynamicSharedMemorySize, SMTOT);
    cudaFuncSetAttribute(gemm_mma<1>, cudaFuncAttributeMaxDynamicSharedMemorySize, SMTOT);

    float *xl1, *xr1, *xl2, *xr2;
    bf16 *a1h, *a1l, *a2h, *a2l, *z2h, *z2l;
    bf16 *bt1lh, *bt1ll, *bt1rh, *bt1rl, *bt2lh, *bt2ll, *bt2rh, *bt2rl, *btdh, *btdl;
    cudaGetSymbolAddress((void**)&xl1,  g_xl1);
    cudaGetSymbolAddress((void**)&xr1,  g_xr1);
    cudaGetSymbolAddress((void**)&xl2,  g_xl2);
    cudaGetSymbolAddress((void**)&xr2,  g_xr2);
    cudaGetSymbolAddress((void**)&a1h,  g_A1h);
    cudaGetSymbolAddress((void**)&a1l,  g_A1l);
    cudaGetSymbolAddress((void**)&a2h,  g_A2h);
    cudaGetSymbolAddress((void**)&a2l,  g_A2l);
    cudaGetSymbolAddress((void**)&z2h,  g_Z2h);
    cudaGetSymbolAddress((void**)&z2l,  g_Z2l);
    cudaGetSymbolAddress((void**)&bt1lh, g_BT1lh);
    cudaGetSymbolAddress((void**)&bt1ll, g_BT1ll);
    cudaGetSymbolAddress((void**)&bt1rh, g_BT1rh);
    cudaGetSymbolAddress((void**)&bt1rl, g_BT1rl);
    cudaGetSymbolAddress((void**)&bt2lh, g_BT2lh);
    cudaGetSymbolAddress((void**)&bt2ll, g_BT2ll);
    cudaGetSymbolAddress((void**)&bt2rh, g_BT2rh);
    cudaGetSymbolAddress((void**)&bt2rl, g_BT2rl);
    cudaGetSymbolAddress((void**)&btdh,  g_BTdh);
    cudaGetSymbolAddress((void**)&btdl,  g_BTdl);

    // 0) CSR build + operand prep
    csr_zero<<<(NN + 1 + 255) / 256, 256>>>();
    csr_hist<<<(EE + 255) / 256, 256>>>(ei);
    csr_scan<<<1, 1024>>>();
    csr_fill<<<(EE + 255) / 256, 256>>>(ei);
    conv_x_kernel<<<(NN * INF_ / 4 + 255) / 256, 256>>>(x);
    {
        dim3 grid(16, 16, 5), blk(32, 8);
        transpose_conv<<<grid, blk>>>(W_l1, W_r1, W_l2, W_r2, W_d1);
    }

    // 1) layer-1 transforms: xl1 = x@W_l1+b_l1, xr1 = x@W_r1+b_r1
    {
        dim3 grid(2 * (C1 / 128), (NN + 127) / 128);
        gemm_mma<0><<<grid, 256, SMTOT>>>(a1h, a1l, nullptr,
                                          bt1lh, bt1ll, bt1rh, bt1rl,
                                          b_l1, b_r1, nullptr, nullptr,
                                          xl1, xr1, NN, INF_, C1);
    }

    // 2) layer-1 fused attention (online softmax, single pass)
    gat1_node<<<(NN * HH * 32 + 255) / 256, 256>>>(att1, bias1);

    // 3) layer-2 transforms
    {
        dim3 grid(2 * (OUTC / 128), (NN + 127) / 128);
        gemm_mma<0><<<grid, 256, SMTOT>>>(a2h, a2l, nullptr,
                                          bt2lh, bt2ll, bt2rh, bt2rl,
                                          b_l2, b_r2, nullptr, nullptr,
                                          xl2, xr2, NN, C1, OUTC);
    }

    // 4) layer-2 fused attention (online softmax, single pass)
    gat2_node<<<(NN * 32 + 255) / 256, 256>>>(att2, bias2);

    // 5) decoder (gather-fused GEMM + gelu + final dot, single kernel)
    {
        dim3 grid(1, (ELL + 127) / 128);
        gemm_mma<1><<<grid, 256, SMTOT>>>(z2h, z2l, eli,
                                          btdh, btdl, nullptr, nullptr,
                                          b_d1, nullptr, W_d2, b_d2,
                                          out, nullptr, ELL, 2 * OUTC, HIDC);
    }
}

// round 15
// speedup vs baseline: 2.6504x; 1.1063x over previous
#include <cuda_runtime.h>
#include <cuda_bf16.h>
#include <cstdint>
#include <cstddef>

#define NN   20000
#define EE   320000
#define ELL  100000
#define INF_ 256
#define HIDC 128
#define OUTC 128
#define HH   4
#define C1   (HH * HIDC)        // 512

typedef __nv_bfloat16 bf16;

// ---------------- scratch (device globals: allocation-free) ----------------
__device__ float g_xl1[(size_t)NN * C1];
__device__ float g_xr1[(size_t)NN * C1];
__device__ float g_xl2[(size_t)NN * OUTC];
__device__ float g_xr2[(size_t)NN * OUTC];
__device__ float g_U[(size_t)NN * HIDC];     // z@Wd1_top + bd1
__device__ float g_V[(size_t)NN * HIDC];     // z@Wd1_bot
__device__ float g_zero[HIDC];               // static zeros (never written)

// CSR by destination (self-loops handled analytically, not stored)
__device__ int g_deg[NN + 1];
__device__ int g_rowptr[NN + 1];
__device__ int g_cursor[NN];
__device__ int g_csr[EE];

// bf16 hi/lo splits of GEMM A operands
__device__ bf16 g_A1h[(size_t)NN * INF_];
__device__ bf16 g_A1l[(size_t)NN * INF_];
__device__ bf16 g_A2h[(size_t)NN * C1];
__device__ bf16 g_A2l[(size_t)NN * C1];
__device__ bf16 g_Z2h[(size_t)NN * OUTC];
__device__ bf16 g_Z2l[(size_t)NN * OUTC];

// transposed bf16 hi/lo weights [N][K]
__device__ bf16 g_BT1lh[C1 * INF_],  g_BT1ll[C1 * INF_];
__device__ bf16 g_BT1rh[C1 * INF_],  g_BT1rl[C1 * INF_];
__device__ bf16 g_BT2lh[OUTC * C1],  g_BT2ll[OUTC * C1];
__device__ bf16 g_BT2rh[OUTC * C1],  g_BT2rl[OUTC * C1];
__device__ bf16 g_BTd0h[HIDC * OUTC], g_BTd0l[HIDC * OUTC];   // Wd1 top^T
__device__ bf16 g_BTd1h[HIDC * OUTC], g_BTd1l[HIDC * OUTC];   // Wd1 bot^T

// ---------------- scalar helpers ----------------
__device__ __forceinline__ float lrelu(float x) { return x >= 0.f ? x : 0.2f * x; }

__device__ __forceinline__ float gelu_t(float x) {
    float x3 = x * x * x;
    return 0.5f * x * (1.f + tanhf(0.7978845608028654f * (x + 0.044715f * x3)));
}

__device__ __forceinline__ void split_bf16(float v, bf16& h, bf16& l) {
    h = __float2bfloat16_rn(v);
    l = __float2bfloat16_rn(v - __bfloat162float(h));
}

// ---------------- PTX helpers ----------------
__device__ __forceinline__ uint32_t smem_u32(const void* p) {
    uint32_t a;
    asm("{ .reg .u64 t; cvta.to.shared.u64 t, %1; cvt.u32.u64 %0, t; }" : "=r"(a) : "l"(p));
    return a;
}

__device__ __forceinline__ void cpa16(uint32_t dst, const void* src, bool pred) {
    int sz = pred ? 16 : 0;
    asm volatile("cp.async.cg.shared.global [%0], [%1], 16, %2;\n"
                 :: "r"(dst), "l"(src), "r"(sz) : "memory");
}

__device__ __forceinline__ void ldm_x4(uint32_t r[4], uint32_t addr) {
    asm volatile("ldmatrix.sync.aligned.m8n8.x4.shared.b16 {%0,%1,%2,%3}, [%4];"
                 : "=r"(r[0]), "=r"(r[1]), "=r"(r[2]), "=r"(r[3]) : "r"(addr));
}

__device__ __forceinline__ void mma_bf16(float c[4], const uint32_t a[4],
                                         uint32_t b0, uint32_t b1) {
    asm volatile("mma.sync.aligned.m16n8k16.row.col.f32.bf16.bf16.f32 "
                 "{%0,%1,%2,%3}, {%4,%5,%6,%7}, {%8,%9}, {%0,%1,%2,%3};"
                 : "+f"(c[0]), "+f"(c[1]), "+f"(c[2]), "+f"(c[3])
                 : "r"(a[0]), "r"(a[1]), "r"(a[2]), "r"(a[3]), "r"(b0), "r"(b1));
}

// ---------------- CSR construction -----------------------------------------
__global__ void csr_zero() {
    int i = blockIdx.x * blockDim.x + threadIdx.x;
    if (i <= NN) g_deg[i] = 0;
}

__global__ void csr_hist(const int* __restrict__ ei) {
    int i = blockIdx.x * blockDim.x + threadIdx.x;
    if (i < EE) atomicAdd(&g_deg[ei[EE + i]], 1);
}

// single-block exclusive scan over NN degree counts -> rowptr + cursor
__global__ __launch_bounds__(1024) void csr_scan() {
    __shared__ int part[1024];
    const int CH = 20;                 // 1024*20 = 20480 >= NN
    int t = threadIdx.x;
    int base = t * CH;
    int local[CH];
    int s = 0;
#pragma unroll
    for (int i = 0; i < CH; i++) {
        int idx = base + i;
        int v = (idx < NN) ? g_deg[idx] : 0;
        local[i] = s;
        s += v;
    }
    part[t] = s;
    __syncthreads();
    for (int d = 1; d < 1024; d <<= 1) {
        int v = (t >= d) ? part[t - d] : 0;
        __syncthreads();
        part[t] += v;
        __syncthreads();
    }
    int off = (t > 0) ? part[t - 1] : 0;
#pragma unroll
    for (int i = 0; i < CH; i++) {
        int idx = base + i;
        if (idx < NN) {
            int r = off + local[i];
            g_rowptr[idx] = r;
            g_cursor[idx] = r;
        }
    }
    if (t == 1023) g_rowptr[NN] = part[1023];
}

__global__ void csr_fill(const int* __restrict__ ei) {
    int i = blockIdx.x * blockDim.x + threadIdx.x;
    if (i >= EE) return;
    int d = ei[EE + i];
    int pos = atomicAdd(&g_cursor[d], 1);
    g_csr[pos] = ei[i];
}

// ---------------- prep: split x into bf16 hi/lo ----------------------------
__global__ void conv_x_kernel(const float* __restrict__ x) {
    int i = blockIdx.x * blockDim.x + threadIdx.x;
    if (i >= NN * INF_ / 4) return;
    float4 v = ((const float4*)x)[i];
    bf16 h0, l0, h1, l1, h2, l2, h3, l3;
    split_bf16(v.x, h0, l0); split_bf16(v.y, h1, l1);
    split_bf16(v.z, h2, l2); split_bf16(v.w, h3, l3);
    __nv_bfloat162* ph = (__nv_bfloat162*)(g_A1h + (size_t)i * 4);
    __nv_bfloat162* pl = (__nv_bfloat162*)(g_A1l + (size_t)i * 4);
    ph[0] = {h0, h1}; ph[1] = {h2, h3};
    pl[0] = {l0, l1}; pl[1] = {l2, l3};
}

// ---------------- prep: transpose + split weights  [K][N] -> [N][K] --------
__global__ void transpose_conv(const float* __restrict__ W_l1, const float* __restrict__ W_r1,
                               const float* __restrict__ W_l2, const float* __restrict__ W_r2,
                               const float* __restrict__ W_d1) {
    __shared__ float ts[32][33];
    const float* W; int Kz, Nz; bf16 *oh, *ol;
    switch (blockIdx.z) {
        case 0:  W = W_l1; Kz = INF_; Nz = C1;   oh = g_BT1lh; ol = g_BT1ll; break;
        case 1:  W = W_r1; Kz = INF_; Nz = C1;   oh = g_BT1rh; ol = g_BT1rl; break;
        case 2:  W = W_l2; Kz = C1;   Nz = OUTC; oh = g_BT2lh; ol = g_BT2ll; break;
        case 3:  W = W_r2; Kz = C1;   Nz = OUTC; oh = g_BT2rh; ol = g_BT2rl; break;
        case 4:  W = W_d1;                 Kz = OUTC; Nz = HIDC; oh = g_BTd0h; ol = g_BTd0l; break;
        default: W = W_d1 + OUTC * HIDC;   Kz = OUTC; Nz = HIDC; oh = g_BTd1h; ol = g_BTd1l; break;
    }
    int k0 = blockIdx.y * 32, n0 = blockIdx.x * 32;
    if (k0 >= Kz || n0 >= Nz) return;
    int tx = threadIdx.x, ty = threadIdx.y;
#pragma unroll
    for (int s = 0; s < 4; s++)
        ts[ty + s * 8][tx] = W[(size_t)(k0 + ty + s * 8) * Nz + n0 + tx];
    __syncthreads();
#pragma unroll
    for (int s = 0; s < 4; s++) {
        int n = n0 + ty + s * 8, k = k0 + tx;
        bf16 h, l;
        split_bf16(ts[tx][ty + s * 8], h, l);
        oh[(size_t)n * Kz + k] = h;
        ol[(size_t)n * Kz + k] = l;
    }
}

// ---------------- HMMA bf16x3 dual-B GEMM -----------------------------------
// 128x128 CTA tile, BK=32, double-buffered cp.async, 8 warps of 64x32.
// C{0,1} = A @ B{0,1}^T + bias{0,1}   (grid.x = 2*Nc/128)
#define LDH 40
#define MATB (128 * LDH * 2)
#define AOFF 1536
#define BOFF (AOFF + 4 * MATB)
#define SMTOT (BOFF + 4 * MATB)

__global__ __launch_bounds__(256, 2) void gemm_mma(
    const bf16* __restrict__ Ah, const bf16* __restrict__ Al,
    const bf16* __restrict__ B0h, const bf16* __restrict__ B0l,
    const bf16* __restrict__ B1h, const bf16* __restrict__ B1l,
    const float* __restrict__ bias0, const float* __restrict__ bias1,
    float* __restrict__ C0, float* __restrict__ C1p,
    int M, int K, int Nc)
{
    extern __shared__ char smem[];
    float* bias_s = (float*)smem;
    uint32_t smb = smem_u32(smem);

    int tid = threadIdx.x, warp = tid >> 5, lane = tid & 31;
    int nb  = Nc >> 7;
    int mat = (blockIdx.x >= nb) ? 1 : 0;
    int bn  = (blockIdx.x - mat * nb) << 7;
    int bm  = (int)blockIdx.y << 7;

    const bf16* Bh = mat ? B1h : B0h;
    const bf16* Bl = mat ? B1l : B0l;
    const float* bias = mat ? bias1 : bias0;
    float* C = mat ? C1p : C0;

    if (tid < 128) bias_s[tid] = bias[bn + tid];

    int lrow = tid >> 2;
    int lko  = (tid & 3) << 3;
    bool aok[2];
    const bf16* gA[2][2];
    const bf16* gB[2][2];
#pragma unroll
    for (int rh = 0; rh < 2; rh++) {
        int r = bm + lrow + rh * 64;
        aok[rh] = r < M;
        int rc = aok[rh] ? r : (M - 1);
        gA[rh][0] = Ah + (size_t)rc * K;
        gA[rh][1] = Al + (size_t)rc * K;
        int br = bn + lrow + rh * 64;
        gB[rh][0] = Bh + (size_t)br * K;
        gB[rh][1] = Bl + (size_t)br * K;
    }

    auto load_stage = [&](int st, int c) {
        int k0h = c << 5;
#pragma unroll
        for (int rh = 0; rh < 2; rh++) {
            int row = lrow + rh * 64;
            uint32_t soff = (uint32_t)(row * LDH + lko) * 2;
#pragma unroll
            for (int h = 0; h < 2; h++) {
                cpa16(smb + AOFF + (uint32_t)(st * 2 + h) * MATB + soff,
                      gA[rh][h] + k0h + lko, aok[rh]);
                cpa16(smb + BOFF + (uint32_t)(st * 2 + h) * MATB + soff,
                      gB[rh][h] + k0h + lko, true);
            }
        }
        asm volatile("cp.async.commit_group;" ::: "memory");
    };

    int wm = (warp >> 2) << 6;
    int wn = (warp & 3) << 5;
    int lr16 = lane & 15;
    int lh8  = (lane >> 4) << 3;

    float acc[4][4][4];
#pragma unroll
    for (int i = 0; i < 4; i++)
#pragma unroll
        for (int j = 0; j < 4; j++)
#pragma unroll
            for (int q = 0; q < 4; q++) acc[i][j][q] = 0.f;

    int nch = K >> 5;
    load_stage(0, 0);
    if (nch > 1) load_stage(1, 1);

    for (int c = 0; c < nch; c++) {
        if (c + 1 < nch) asm volatile("cp.async.wait_group 1;" ::: "memory");
        else             asm volatile("cp.async.wait_group 0;" ::: "memory");
        __syncthreads();

        int st = c & 1;
        uint32_t aBh = smb + AOFF + (uint32_t)(st * 2 + 0) * MATB;
        uint32_t aBl = smb + AOFF + (uint32_t)(st * 2 + 1) * MATB;
        uint32_t bBh = smb + BOFF + (uint32_t)(st * 2 + 0) * MATB;
        uint32_t bBl = smb + BOFF + (uint32_t)(st * 2 + 1) * MATB;

#pragma unroll
        for (int ks = 0; ks < 2; ks++) {
            int kin = ks * 16 + lh8;
            uint32_t b_h[2][4], b_l[2][4];
#pragma unroll
            for (int np = 0; np < 2; np++) {
                uint32_t off = (uint32_t)((wn + np * 16 + lr16) * LDH + kin) * 2;
                ldm_x4(b_h[np], bBh + off);
                ldm_x4(b_l[np], bBl + off);
            }
#pragma unroll
            for (int mf = 0; mf < 4; mf++) {
                uint32_t a_h[4], a_l[4];
                uint32_t off = (uint32_t)((wm + mf * 16 + lr16) * LDH + kin) * 2;
                ldm_x4(a_h, aBh + off);
                ldm_x4(a_l, aBl + off);
#pragma unroll
                for (int nf = 0; nf < 4; nf++) {
                    int np = nf >> 1, s = nf & 1;
                    uint32_t bh0 = b_h[np][s], bh1 = b_h[np][2 + s];
                    uint32_t bl0 = b_l[np][s], bl1 = b_l[np][2 + s];
                    mma_bf16(acc[mf][nf], a_h, bh0, bh1);
                    mma_bf16(acc[mf][nf], a_l, bh0, bh1);
                    mma_bf16(acc[mf][nf], a_h, bl0, bl1);
                }
            }
        }
        __syncthreads();
        if (c + 2 < nch) load_stage((c + 2) & 1, c + 2);
    }

    int grp = lane >> 2, t4 = lane & 3;
#pragma unroll
    for (int mf = 0; mf < 4; mf++) {
        int r0 = bm + wm + mf * 16 + grp;
#pragma unroll
        for (int nf = 0; nf < 4; nf++) {
            int colL = wn + nf * 8 + t4 * 2;
            float b0 = bias_s[colL], b1 = bias_s[colL + 1];
            if (r0 < M)
                *(float2*)(C + (size_t)r0 * Nc + bn + colL) =
                    make_float2(acc[mf][nf][0] + b0, acc[mf][nf][1] + b1);
            if (r0 + 8 < M)
                *(float2*)(C + (size_t)(r0 + 8) * Nc + bn + colL) =
                    make_float2(acc[mf][nf][2] + b0, acc[mf][nf][3] + b1);
        }
    }
}

// ---------------- fused GATv2 edge phase, layer 1 (online softmax) ----------
__global__ __launch_bounds__(256) void gat1_node(const float* __restrict__ att,
                                                 const float* __restrict__ bias1)
{
    int w = (blockIdx.x * blockDim.x + threadIdx.x) >> 5;
    if (w >= NN * HH) return;
    int n = w >> 2, h = w & 3;
    int lane = threadIdx.x & 31;
    int off = h * HIDC + lane * 4;

    float4 xr = *(const float4*)(g_xr1 + (size_t)n * C1 + off);
    float4 at = *(const float4*)(att + off);
    float4 vs = *(const float4*)(g_xl1 + (size_t)n * C1 + off);

    int beg = g_rowptr[n], end = g_rowptr[n + 1];

    auto logit4 = [&](float4 v) -> float {
        float p = lrelu(v.x + xr.x) * at.x + lrelu(v.y + xr.y) * at.y +
                  lrelu(v.z + xr.z) * at.z + lrelu(v.w + xr.w) * at.w;
        p += __shfl_xor_sync(0xffffffffu, p, 16);
        p += __shfl_xor_sync(0xffffffffu, p, 8);
        p += __shfl_xor_sync(0xffffffffu, p, 4);
        p += __shfl_xor_sync(0xffffffffu, p, 2);
        p += __shfl_xor_sync(0xffffffffu, p, 1);
        return p;
    };

    float m = logit4(vs);
    float sum = 1.f;
    float4 acc = vs;

#pragma unroll 2
    for (int j = beg; j < end; j++) {
        int s = __ldg(&g_csr[j]);
        float4 v = *(const float4*)(g_xl1 + (size_t)s * C1 + off);
        float l = logit4(v);
        float nm = fmaxf(m, l);
        float sc = __expf(m - nm);
        float e  = __expf(l - nm);
        sum = sum * sc + e;
        acc.x = acc.x * sc + e * v.x;
        acc.y = acc.y * sc + e * v.y;
        acc.z = acc.z * sc + e * v.z;
        acc.w = acc.w * sc + e * v.w;
        m = nm;
    }

    float4 b = *(const float4*)(bias1 + off);
    float o0 = gelu_t(acc.x / sum + b.x);
    float o1 = gelu_t(acc.y / sum + b.y);
    float o2 = gelu_t(acc.z / sum + b.z);
    float o3 = gelu_t(acc.w / sum + b.w);
    bf16 h0, l0, h1, l1, h2, l2, h3, l3;
    split_bf16(o0, h0, l0); split_bf16(o1, h1, l1);
    split_bf16(o2, h2, l2); split_bf16(o3, h3, l3);
    __nv_bfloat162* ph = (__nv_bfloat162*)(g_A2h + (size_t)n * C1 + off);
    __nv_bfloat162* pl = (__nv_bfloat162*)(g_A2l + (size_t)n * C1 + off);
    ph[0] = {h0, h1}; ph[1] = {h2, h3};
    pl[0] = {l0, l1}; pl[1] = {l2, l3};
}

// ---------------- fused GATv2 edge phase, layer 2 (H=1, online softmax) -----
__global__ __launch_bounds__(256) void gat2_node(const float* __restrict__ att2,
                                                 const float* __restrict__ bias2)
{
    int n = (blockIdx.x * blockDim.x + threadIdx.x) >> 5;
    if (n >= NN) return;
    int lane = threadIdx.x & 31;
    int off = lane * 4;

    float4 xr = *(const float4*)(g_xr2 + (size_t)n * OUTC + off);
    float4 at = *(const float4*)(att2 + off);
    float4 vs = *(const float4*)(g_xl2 + (size_t)n * OUTC + off);

    int beg = g_rowptr[n], end = g_rowptr[n + 1];

    auto logit4 = [&](float4 v) -> float {
        float p = lrelu(v.x + xr.x) * at.x + lrelu(v.y + xr.y) * at.y +
                  lrelu(v.z + xr.z) * at.z + lrelu(v.w + xr.w) * at.w;
        p += __shfl_xor_sync(0xffffffffu, p, 16);
        p += __shfl_xor_sync(0xffffffffu, p, 8);
        p += __shfl_xor_sync(0xffffffffu, p, 4);
        p += __shfl_xor_sync(0xffffffffu, p, 2);
        p += __shfl_xor_sync(0xffffffffu, p, 1);
        return p;
    };

    float m = logit4(vs);
    float sum = 1.f;
    float4 acc = vs;

#pragma unroll 2
    for (int j = beg; j < end; j++) {
        int s = __ldg(&g_csr[j]);
        float4 v = *(const float4*)(g_xl2 + (size_t)s * OUTC + off);
        float l = logit4(v);
        float nm = fmaxf(m, l);
        float sc = __expf(m - nm);
        float e  = __expf(l - nm);
        sum = sum * sc + e;
        acc.x = acc.x * sc + e * v.x;
        acc.y = acc.y * sc + e * v.y;
        acc.z = acc.z * sc + e * v.z;
        acc.w = acc.w * sc + e * v.w;
        m = nm;
    }

    float4 b = *(const float4*)(bias2 + off);
    float o0 = acc.x / sum + b.x;
    float o1 = acc.y / sum + b.y;
    float o2 = acc.z / sum + b.z;
    float o3 = acc.w / sum + b.w;
    bf16 h0, l0, h1, l1, h2, l2, h3, l3;
    split_bf16(o0, h0, l0); split_bf16(o1, h1, l1);
    split_bf16(o2, h2, l2); split_bf16(o3, h3, l3);
    __nv_bfloat162* ph = (__nv_bfloat162*)(g_Z2h + (size_t)n * OUTC + off);
    __nv_bfloat162* pl = (__nv_bfloat162*)(g_Z2l + (size_t)n * OUTC + off);
    ph[0] = {h0, h1}; ph[1] = {h2, h3};
    pl[0] = {l0, l1}; pl[1] = {l2, l3};
}

// ---------------- decoder edge kernel: out[e] = gelu(U[a]+V[b]).wd2 + bd2 ---
__global__ __launch_bounds__(256) void dec_edge(const int* __restrict__ eli,
                                                const float* __restrict__ wd2,
                                                const float* __restrict__ bd2,
                                                float* __restrict__ out)
{
    int e = (blockIdx.x * blockDim.x + threadIdx.x) >> 5;
    if (e >= ELL) return;
    int lane = threadIdx.x & 31;
    int a = __ldg(&eli[e]);
    int b = __ldg(&eli[ELL + e]);
    float4 u = *(const float4*)(g_U + (size_t)a * HIDC + lane * 4);
    float4 v = *(const float4*)(g_V + (size_t)b * HIDC + lane * 4);
    float4 w = *(const float4*)(wd2 + lane * 4);
    float s = gelu_t(u.x + v.x) * w.x + gelu_t(u.y + v.y) * w.y +
              gelu_t(u.z + v.z) * w.z + gelu_t(u.w + v.w) * w.w;
    s += __shfl_xor_sync(0xffffffffu, s, 16);
    s += __shfl_xor_sync(0xffffffffu, s, 8);
    s += __shfl_xor_sync(0xffffffffu, s, 4);
    s += __shfl_xor_sync(0xffffffffu, s, 2);
    s += __shfl_xor_sync(0xffffffffu, s, 1);
    if (lane == 0) out[e] = s + bd2[0];
}

// ---------------- launch ----------------------------------------------------
extern "C" void kernel_launch(void* const* d_in, const int* in_sizes, int n_in,
                              void* d_out, int out_size)
{
    const float* x     = (const float*)d_in[0];
    const int*   ei    = (const int*)d_in[1];
    const int*   eli   = (const int*)d_in[2];
    const float* W_l1  = (const float*)d_in[3];
    const float* b_l1  = (const float*)d_in[4];
    const float* W_r1  = (const float*)d_in[5];
    const float* b_r1  = (const float*)d_in[6];
    const float* att1  = (const float*)d_in[7];
    const float* bias1 = (const float*)d_in[8];
    const float* W_l2  = (const float*)d_in[9];
    const float* b_l2  = (const float*)d_in[10];
    const float* W_r2  = (const float*)d_in[11];
    const float* b_r2  = (const float*)d_in[12];
    const float* att2  = (const float*)d_in[13];
    const float* bias2 = (const float*)d_in[14];
    const float* W_d1  = (const float*)d_in[15];
    const float* b_d1  = (const float*)d_in[16];
    const float* W_d2  = (const float*)d_in[17];
    const float* b_d2  = (const float*)d_in[18];
    float* out = (float*)d_out;

    cudaFuncSetAttribute(gemm_mma, cudaFuncAttributeMaxDynamicSharedMemorySize, SMTOT);

    float *xl1, *xr1, *xl2, *xr2, *uu, *vv, *zr;
    bf16 *a1h, *a1l, *a2h, *a2l, *z2h, *z2l;
    bf16 *bt1lh, *bt1ll, *bt1rh, *bt1rl, *bt2lh, *bt2ll, *bt2rh, *bt2rl;
    bf16 *btd0h, *btd0l, *btd1h, *btd1l;
    cudaGetSymbolAddress((void**)&xl1,  g_xl1);
    cudaGetSymbolAddress((void**)&xr1,  g_xr1);
    cudaGetSymbolAddress((void**)&xl2,  g_xl2);
    cudaGetSymbolAddress((void**)&xr2,  g_xr2);
    cudaGetSymbolAddress((void**)&uu,   g_U);
    cudaGetSymbolAddress((void**)&vv,   g_V);
    cudaGetSymbolAddress((void**)&zr,   g_zero);
    cudaGetSymbolAddress((void**)&a1h,  g_A1h);
    cudaGetSymbolAddress((void**)&a1l,  g_A1l);
    cudaGetSymbolAddress((void**)&a2h,  g_A2h);
    cudaGetSymbolAddress((void**)&a2l,  g_A2l);
    cudaGetSymbolAddress((void**)&z2h,  g_Z2h);
    cudaGetSymbolAddress((void**)&z2l,  g_Z2l);
    cudaGetSymbolAddress((void**)&bt1lh, g_BT1lh);
    cudaGetSymbolAddress((void**)&bt1ll, g_BT1ll);
    cudaGetSymbolAddress((void**)&bt1rh, g_BT1rh);
    cudaGetSymbolAddress((void**)&bt1rl, g_BT1rl);
    cudaGetSymbolAddress((void**)&bt2lh, g_BT2lh);
    cudaGetSymbolAddress((void**)&bt2ll, g_BT2ll);
    cudaGetSymbolAddress((void**)&bt2rh, g_BT2rh);
    cudaGetSymbolAddress((void**)&bt2rl, g_BT2rl);
    cudaGetSymbolAddress((void**)&btd0h, g_BTd0h);
    cudaGetSymbolAddress((void**)&btd0l, g_BTd0l);
    cudaGetSymbolAddress((void**)&btd1h, g_BTd1h);
    cudaGetSymbolAddress((void**)&btd1l, g_BTd1l);

    // 0) CSR build + operand prep
    csr_zero<<<(NN + 1 + 255) / 256, 256>>>();
    csr_hist<<<(EE + 255) / 256, 256>>>(ei);
    csr_scan<<<1, 1024>>>();
    csr_fill<<<(EE + 255) / 256, 256>>>(ei);
    conv_x_kernel<<<(NN * INF_ / 4 + 255) / 256, 256>>>(x);
    {
        dim3 grid(16, 16, 6), blk(32, 8);
        transpose_conv<<<grid, blk>>>(W_l1, W_r1, W_l2, W_r2, W_d1);
    }

    // 1) layer-1 transforms: xl1 = x@W_l1+b_l1, xr1 = x@W_r1+b_r1
    {
        dim3 grid(2 * (C1 / 128), (NN + 127) / 128);
        gemm_mma<<<grid, 256, SMTOT>>>(a1h, a1l,
                                       bt1lh, bt1ll, bt1rh, bt1rl,
                                       b_l1, b_r1, xl1, xr1, NN, INF_, C1);
    }

    // 2) layer-1 fused attention (online softmax, single pass)
    gat1_node<<<(NN * HH * 32 + 255) / 256, 256>>>(att1, bias1);

    // 3) layer-2 transforms
    {
        dim3 grid(2 * (OUTC / 128), (NN + 127) / 128);
        gemm_mma<<<grid, 256, SMTOT>>>(a2h, a2l,
                                       bt2lh, bt2ll, bt2rh, bt2rl,
                                       b_l2, b_r2, xl2, xr2, NN, C1, OUTC);
    }

    // 4) layer-2 fused attention (online softmax, single pass)
    gat2_node<<<(NN * 32 + 255) / 256, 256>>>(att2, bias2);

    // 5) decoder: per-node U = z@Wd1_top + bd1, V = z@Wd1_bot  (dual-B GEMM)
    {
        dim3 grid(2 * (HIDC / 128), (NN + 127) / 128);
        gemm_mma<<<grid, 256, SMTOT>>>(z2h, z2l,
                                       btd0h, btd0l, btd1h, btd1l,
                                       b_d1, zr, uu, vv, NN, OUTC, HIDC);
    }

    // 6) decoder edge kernel: out[e] = gelu(U[a]+V[b]).wd2 + bd2
    dec_edge<<<((ELL * 32) + 255) / 256, 256>>>(eli, W_d2, b_d2, out);
}

// round 16
// speedup vs baseline: 2.7976x; 1.0555x over previous
#include <cuda_runtime.h>
#include <cuda_bf16.h>
#include <cstdint>
#include <cstddef>

#define NN   20000
#define EE   320000
#define ELL  100000
#define INF_ 256
#define HIDC 128
#define OUTC 128
#define HH   4
#define C1   (HH * HIDC)        // 512

typedef __nv_bfloat16 bf16;

// ---------------- scratch (device globals: allocation-free) ----------------
__device__ float g_xl1[(size_t)NN * C1];
__device__ float g_xr1[(size_t)NN * C1];
__device__ float g_xl2[(size_t)NN * OUTC];
__device__ float g_xr2[(size_t)NN * OUTC];
__device__ float g_U[(size_t)NN * HIDC];     // z@Wd1_top + bd1
__device__ float g_V[(size_t)NN * HIDC];     // z@Wd1_bot
__device__ float g_zero[HIDC];               // static zeros (never written)

// CSR by destination (self-loops handled analytically, not stored)
__device__ int g_deg[NN + 1];
__device__ int g_rowptr[NN + 1];
__device__ int g_cursor[NN];
__device__ int g_csr[EE];

// bf16 hi/lo splits of GEMM A operands
__device__ bf16 g_A1h[(size_t)NN * INF_];
__device__ bf16 g_A1l[(size_t)NN * INF_];
__device__ bf16 g_A2h[(size_t)NN * C1];
__device__ bf16 g_A2l[(size_t)NN * C1];
__device__ bf16 g_Z2h[(size_t)NN * OUTC];
__device__ bf16 g_Z2l[(size_t)NN * OUTC];

// transposed bf16 hi/lo weights [N][K]
__device__ bf16 g_BT1lh[C1 * INF_],  g_BT1ll[C1 * INF_];
__device__ bf16 g_BT1rh[C1 * INF_],  g_BT1rl[C1 * INF_];
__device__ bf16 g_BT2lh[OUTC * C1],  g_BT2ll[OUTC * C1];
__device__ bf16 g_BT2rh[OUTC * C1],  g_BT2rl[OUTC * C1];
__device__ bf16 g_BTd0h[HIDC * OUTC], g_BTd0l[HIDC * OUTC];   // Wd1 top^T
__device__ bf16 g_BTd1h[HIDC * OUTC], g_BTd1l[HIDC * OUTC];   // Wd1 bot^T

// ---------------- scalar helpers ----------------
__device__ __forceinline__ float lrelu(float x) { return x >= 0.f ? x : 0.2f * x; }

__device__ __forceinline__ float gelu_t(float x) {
    float x3 = x * x * x;
    return 0.5f * x * (1.f + tanhf(0.7978845608028654f * (x + 0.044715f * x3)));
}

__device__ __forceinline__ void split_bf16(float v, bf16& h, bf16& l) {
    h = __float2bfloat16_rn(v);
    l = __float2bfloat16_rn(v - __bfloat162float(h));
}

// ---------------- PTX helpers ----------------
__device__ __forceinline__ uint32_t smem_u32(const void* p) {
    uint32_t a;
    asm("{ .reg .u64 t; cvta.to.shared.u64 t, %1; cvt.u32.u64 %0, t; }" : "=r"(a) : "l"(p));
    return a;
}

__device__ __forceinline__ void cpa16(uint32_t dst, const void* src, bool pred) {
    int sz = pred ? 16 : 0;
    asm volatile("cp.async.cg.shared.global [%0], [%1], 16, %2;\n"
                 :: "r"(dst), "l"(src), "r"(sz) : "memory");
}

__device__ __forceinline__ void ldm_x4(uint32_t r[4], uint32_t addr) {
    asm volatile("ldmatrix.sync.aligned.m8n8.x4.shared.b16 {%0,%1,%2,%3}, [%4];"
                 : "=r"(r[0]), "=r"(r[1]), "=r"(r[2]), "=r"(r[3]) : "r"(addr));
}

__device__ __forceinline__ void mma_bf16(float c[4], const uint32_t a[4],
                                         uint32_t b0, uint32_t b1) {
    asm volatile("mma.sync.aligned.m16n8k16.row.col.f32.bf16.bf16.f32 "
                 "{%0,%1,%2,%3}, {%4,%5,%6,%7}, {%8,%9}, {%0,%1,%2,%3};"
                 : "+f"(c[0]), "+f"(c[1]), "+f"(c[2]), "+f"(c[3])
                 : "r"(a[0]), "r"(a[1]), "r"(a[2]), "r"(a[3]), "r"(b0), "r"(b1));
}

// ---------------- CSR construction -----------------------------------------
__global__ void csr_hist(const int* __restrict__ ei) {
    int i = blockIdx.x * blockDim.x + threadIdx.x;
    if (i < EE) atomicAdd(&g_deg[ei[EE + i]], 1);
}

// single-block exclusive scan over NN degree counts -> rowptr + cursor
__global__ __launch_bounds__(1024) void csr_scan() {
    __shared__ int part[1024];
    const int CH = 20;                 // 1024*20 = 20480 >= NN
    int t = threadIdx.x;
    int base = t * CH;
    int local[CH];
    int s = 0;
#pragma unroll
    for (int i = 0; i < CH; i++) {
        int idx = base + i;
        int v = (idx < NN) ? g_deg[idx] : 0;
        local[i] = s;
        s += v;
    }
    part[t] = s;
    __syncthreads();
    for (int d = 1; d < 1024; d <<= 1) {
        int v = (t >= d) ? part[t - d] : 0;
        __syncthreads();
        part[t] += v;
        __syncthreads();
    }
    int off = (t > 0) ? part[t - 1] : 0;
#pragma unroll
    for (int i = 0; i < CH; i++) {
        int idx = base + i;
        if (idx < NN) {
            int r = off + local[i];
            g_rowptr[idx] = r;
            g_cursor[idx] = r;
        }
    }
    if (t == 1023) g_rowptr[NN] = part[1023];
}

__global__ void csr_fill(const int* __restrict__ ei) {
    int i = blockIdx.x * blockDim.x + threadIdx.x;
    if (i >= EE) return;
    int d = ei[EE + i];
    int pos = atomicAdd(&g_cursor[d], 1);
    g_csr[pos] = ei[i];
}

// ---------------- prep: split x into bf16 hi/lo + zero deg ------------------
__global__ void conv_x_kernel(const float* __restrict__ x) {
    int i = blockIdx.x * blockDim.x + threadIdx.x;
    if (i <= NN) g_deg[i] = 0;          // fused csr_zero
    if (i >= NN * INF_ / 4) return;
    float4 v = ((const float4*)x)[i];
    bf16 h0, l0, h1, l1, h2, l2, h3, l3;
    split_bf16(v.x, h0, l0); split_bf16(v.y, h1, l1);
    split_bf16(v.z, h2, l2); split_bf16(v.w, h3, l3);
    __nv_bfloat162* ph = (__nv_bfloat162*)(g_A1h + (size_t)i * 4);
    __nv_bfloat162* pl = (__nv_bfloat162*)(g_A1l + (size_t)i * 4);
    ph[0] = {h0, h1}; ph[1] = {h2, h3};
    pl[0] = {l0, l1}; pl[1] = {l2, l3};
}

// ---------------- prep: transpose + split weights  [K][N] -> [N][K] --------
__global__ void transpose_conv(const float* __restrict__ W_l1, const float* __restrict__ W_r1,
                               const float* __restrict__ W_l2, const float* __restrict__ W_r2,
                               const float* __restrict__ W_d1) {
    __shared__ float ts[32][33];
    const float* W; int Kz, Nz; bf16 *oh, *ol;
    switch (blockIdx.z) {
        case 0:  W = W_l1; Kz = INF_; Nz = C1;   oh = g_BT1lh; ol = g_BT1ll; break;
        case 1:  W = W_r1; Kz = INF_; Nz = C1;   oh = g_BT1rh; ol = g_BT1rl; break;
        case 2:  W = W_l2; Kz = C1;   Nz = OUTC; oh = g_BT2lh; ol = g_BT2ll; break;
        case 3:  W = W_r2; Kz = C1;   Nz = OUTC; oh = g_BT2rh; ol = g_BT2rl; break;
        case 4:  W = W_d1;                 Kz = OUTC; Nz = HIDC; oh = g_BTd0h; ol = g_BTd0l; break;
        default: W = W_d1 + OUTC * HIDC;   Kz = OUTC; Nz = HIDC; oh = g_BTd1h; ol = g_BTd1l; break;
    }
    int k0 = blockIdx.y * 32, n0 = blockIdx.x * 32;
    if (k0 >= Kz || n0 >= Nz) return;
    int tx = threadIdx.x, ty = threadIdx.y;
#pragma unroll
    for (int s = 0; s < 4; s++)
        ts[ty + s * 8][tx] = W[(size_t)(k0 + ty + s * 8) * Nz + n0 + tx];
    __syncthreads();
#pragma unroll
    for (int s = 0; s < 4; s++) {
        int n = n0 + ty + s * 8, k = k0 + tx;
        bf16 h, l;
        split_bf16(ts[tx][ty + s * 8], h, l);
        oh[(size_t)n * Kz + k] = h;
        ol[(size_t)n * Kz + k] = l;
    }
}

// ---------------- HMMA bf16x3 dual-B GEMM -----------------------------------
// 128x128 CTA tile, BK=32, double-buffered cp.async, 8 warps of 64x32.
// C{0,1} = A @ B{0,1}^T + bias{0,1}   (grid.x = 2*Nc/128)
#define LDH 40
#define MATB (128 * LDH * 2)
#define AOFF 1536
#define BOFF (AOFF + 4 * MATB)
#define SMTOT (BOFF + 4 * MATB)

__global__ __launch_bounds__(256, 2) void gemm_mma(
    const bf16* __restrict__ Ah, const bf16* __restrict__ Al,
    const bf16* __restrict__ B0h, const bf16* __restrict__ B0l,
    const bf16* __restrict__ B1h, const bf16* __restrict__ B1l,
    const float* __restrict__ bias0, const float* __restrict__ bias1,
    float* __restrict__ C0, float* __restrict__ C1p,
    int M, int K, int Nc)
{
    extern __shared__ char smem[];
    float* bias_s = (float*)smem;
    uint32_t smb = smem_u32(smem);

    int tid = threadIdx.x, warp = tid >> 5, lane = tid & 31;
    int nb  = Nc >> 7;
    int mat = (blockIdx.x >= nb) ? 1 : 0;
    int bn  = (blockIdx.x - mat * nb) << 7;
    int bm  = (int)blockIdx.y << 7;

    const bf16* Bh = mat ? B1h : B0h;
    const bf16* Bl = mat ? B1l : B0l;
    const float* bias = mat ? bias1 : bias0;
    float* C = mat ? C1p : C0;

    if (tid < 128) bias_s[tid] = bias[bn + tid];

    int lrow = tid >> 2;
    int lko  = (tid & 3) << 3;
    bool aok[2];
    const bf16* gA[2][2];
    const bf16* gB[2][2];
#pragma unroll
    for (int rh = 0; rh < 2; rh++) {
        int r = bm + lrow + rh * 64;
        aok[rh] = r < M;
        int rc = aok[rh] ? r : (M - 1);
        gA[rh][0] = Ah + (size_t)rc * K;
        gA[rh][1] = Al + (size_t)rc * K;
        int br = bn + lrow + rh * 64;
        gB[rh][0] = Bh + (size_t)br * K;
        gB[rh][1] = Bl + (size_t)br * K;
    }

    auto load_stage = [&](int st, int c) {
        int k0h = c << 5;
#pragma unroll
        for (int rh = 0; rh < 2; rh++) {
            int row = lrow + rh * 64;
            uint32_t soff = (uint32_t)(row * LDH + lko) * 2;
#pragma unroll
            for (int h = 0; h < 2; h++) {
                cpa16(smb + AOFF + (uint32_t)(st * 2 + h) * MATB + soff,
                      gA[rh][h] + k0h + lko, aok[rh]);
                cpa16(smb + BOFF + (uint32_t)(st * 2 + h) * MATB + soff,
                      gB[rh][h] + k0h + lko, true);
            }
        }
        asm volatile("cp.async.commit_group;" ::: "memory");
    };

    int wm = (warp >> 2) << 6;
    int wn = (warp & 3) << 5;
    int lr16 = lane & 15;
    int lh8  = (lane >> 4) << 3;

    float acc[4][4][4];
#pragma unroll
    for (int i = 0; i < 4; i++)
#pragma unroll
        for (int j = 0; j < 4; j++)
#pragma unroll
            for (int q = 0; q < 4; q++) acc[i][j][q] = 0.f;

    int nch = K >> 5;
    load_stage(0, 0);
    if (nch > 1) load_stage(1, 1);

    for (int c = 0; c < nch; c++) {
        if (c + 1 < nch) asm volatile("cp.async.wait_group 1;" ::: "memory");
        else             asm volatile("cp.async.wait_group 0;" ::: "memory");
        __syncthreads();

        int st = c & 1;
        uint32_t aBh = smb + AOFF + (uint32_t)(st * 2 + 0) * MATB;
        uint32_t aBl = smb + AOFF + (uint32_t)(st * 2 + 1) * MATB;
        uint32_t bBh = smb + BOFF + (uint32_t)(st * 2 + 0) * MATB;
        uint32_t bBl = smb + BOFF + (uint32_t)(st * 2 + 1) * MATB;

#pragma unroll
        for (int ks = 0; ks < 2; ks++) {
            int kin = ks * 16 + lh8;
            uint32_t b_h[2][4], b_l[2][4];
#pragma unroll
            for (int np = 0; np < 2; np++) {
                uint32_t off = (uint32_t)((wn + np * 16 + lr16) * LDH + kin) * 2;
                ldm_x4(b_h[np], bBh + off);
                ldm_x4(b_l[np], bBl + off);
            }
#pragma unroll
            for (int mf = 0; mf < 4; mf++) {
                uint32_t a_h[4], a_l[4];
                uint32_t off = (uint32_t)((wm + mf * 16 + lr16) * LDH + kin) * 2;
                ldm_x4(a_h, aBh + off);
                ldm_x4(a_l, aBl + off);
                // term-grouped: 4-MMA dependency distance on each accumulator
#pragma unroll
                for (int nf = 0; nf < 4; nf++) {
                    int np = nf >> 1, s = nf & 1;
                    mma_bf16(acc[mf][nf], a_h, b_h[np][s], b_h[np][2 + s]);
                }
#pragma unroll
                for (int nf = 0; nf < 4; nf++) {
                    int np = nf >> 1, s = nf & 1;
                    mma_bf16(acc[mf][nf], a_l, b_h[np][s], b_h[np][2 + s]);
                }
#pragma unroll
                for (int nf = 0; nf < 4; nf++) {
                    int np = nf >> 1, s = nf & 1;
                    mma_bf16(acc[mf][nf], a_h, b_l[np][s], b_l[np][2 + s]);
                }
            }
        }
        __syncthreads();
        if (c + 2 < nch) load_stage((c + 2) & 1, c + 2);
    }

    int grp = lane >> 2, t4 = lane & 3;
#pragma unroll
    for (int mf = 0; mf < 4; mf++) {
        int r0 = bm + wm + mf * 16 + grp;
#pragma unroll
        for (int nf = 0; nf < 4; nf++) {
            int colL = wn + nf * 8 + t4 * 2;
            float b0 = bias_s[colL], b1 = bias_s[colL + 1];
            if (r0 < M)
                *(float2*)(C + (size_t)r0 * Nc + bn + colL) =
                    make_float2(acc[mf][nf][0] + b0, acc[mf][nf][1] + b1);
            if (r0 + 8 < M)
                *(float2*)(C + (size_t)(r0 + 8) * Nc + bn + colL) =
                    make_float2(acc[mf][nf][2] + b0, acc[mf][nf][3] + b1);
        }
    }
}

// ---------------- fused GATv2 edge phase, layer 1 (online softmax) ----------
// One warp per (node, head); 2-edge unrolled: paired gathers + interleaved
// shuffle-reduction chains; sequential online updates (numerics unchanged).
__global__ __launch_bounds__(256) void gat1_node(const float* __restrict__ att,
                                                 const float* __restrict__ bias1)
{
    int w = (blockIdx.x * blockDim.x + threadIdx.x) >> 5;
    if (w >= NN * HH) return;
    int n = w >> 2, h = w & 3;
    int lane = threadIdx.x & 31;
    int off = h * HIDC + lane * 4;

    float4 xr = *(const float4*)(g_xr1 + (size_t)n * C1 + off);
    float4 at = *(const float4*)(att + off);
    float4 vs = *(const float4*)(g_xl1 + (size_t)n * C1 + off);

    int beg = __ldg(&g_rowptr[n]), end = __ldg(&g_rowptr[n + 1]);

    auto partial = [&](float4 v) -> float {
        return lrelu(v.x + xr.x) * at.x + lrelu(v.y + xr.y) * at.y +
               lrelu(v.z + xr.z) * at.z + lrelu(v.w + xr.w) * at.w;
    };

    float m, sum;
    float4 acc;
    {
        float p = partial(vs);
        p += __shfl_xor_sync(0xffffffffu, p, 16);
        p += __shfl_xor_sync(0xffffffffu, p, 8);
        p += __shfl_xor_sync(0xffffffffu, p, 4);
        p += __shfl_xor_sync(0xffffffffu, p, 2);
        p += __shfl_xor_sync(0xffffffffu, p, 1);
        m = p; sum = 1.f; acc = vs;
    }

    auto update = [&](float l, float4 v) {
        float nm = fmaxf(m, l);
        float sc = __expf(m - nm);
        float e  = __expf(l - nm);
        sum = sum * sc + e;
        acc.x = acc.x * sc + e * v.x;
        acc.y = acc.y * sc + e * v.y;
        acc.z = acc.z * sc + e * v.z;
        acc.w = acc.w * sc + e * v.w;
        m = nm;
    };

    int j = beg;
    for (; j + 1 < end; j += 2) {
        int s0 = __ldg(&g_csr[j]);
        int s1 = __ldg(&g_csr[j + 1]);
        float4 v0 = *(const float4*)(g_xl1 + (size_t)s0 * C1 + off);
        float4 v1 = *(const float4*)(g_xl1 + (size_t)s1 * C1 + off);
        float p0 = partial(v0);
        float p1 = partial(v1);
#pragma unroll
        for (int d = 16; d >= 1; d >>= 1) {
            p0 += __shfl_xor_sync(0xffffffffu, p0, d);
            p1 += __shfl_xor_sync(0xffffffffu, p1, d);
        }
        update(p0, v0);
        update(p1, v1);
    }
    if (j < end) {
        int s0 = __ldg(&g_csr[j]);
        float4 v0 = *(const float4*)(g_xl1 + (size_t)s0 * C1 + off);
        float p0 = partial(v0);
#pragma unroll
        for (int d = 16; d >= 1; d >>= 1)
            p0 += __shfl_xor_sync(0xffffffffu, p0, d);
        update(p0, v0);
    }

    float4 b = *(const float4*)(bias1 + off);
    float o0 = gelu_t(acc.x / sum + b.x);
    float o1 = gelu_t(acc.y / sum + b.y);
    float o2 = gelu_t(acc.z / sum + b.z);
    float o3 = gelu_t(acc.w / sum + b.w);
    bf16 h0, l0, h1, l1, h2, l2, h3, l3;
    split_bf16(o0, h0, l0); split_bf16(o1, h1, l1);
    split_bf16(o2, h2, l2); split_bf16(o3, h3, l3);
    __nv_bfloat162* ph = (__nv_bfloat162*)(g_A2h + (size_t)n * C1 + off);
    __nv_bfloat162* pl = (__nv_bfloat162*)(g_A2l + (size_t)n * C1 + off);
    ph[0] = {h0, h1}; ph[1] = {h2, h3};
    pl[0] = {l0, l1}; pl[1] = {l2, l3};
}

// ---------------- fused GATv2 edge phase, layer 2 (H=1, online softmax) -----
__global__ __launch_bounds__(256) void gat2_node(const float* __restrict__ att2,
                                                 const float* __restrict__ bias2)
{
    int n = (blockIdx.x * blockDim.x + threadIdx.x) >> 5;
    if (n >= NN) return;
    int lane = threadIdx.x & 31;
    int off = lane * 4;

    float4 xr = *(const float4*)(g_xr2 + (size_t)n * OUTC + off);
    float4 at = *(const float4*)(att2 + off);
    float4 vs = *(const float4*)(g_xl2 + (size_t)n * OUTC + off);

    int beg = __ldg(&g_rowptr[n]), end = __ldg(&g_rowptr[n + 1]);

    auto partial = [&](float4 v) -> float {
        return lrelu(v.x + xr.x) * at.x + lrelu(v.y + xr.y) * at.y +
               lrelu(v.z + xr.z) * at.z + lrelu(v.w + xr.w) * at.w;
    };

    float m, sum;
    float4 acc;
    {
        float p = partial(vs);
        p += __shfl_xor_sync(0xffffffffu, p, 16);
        p += __shfl_xor_sync(0xffffffffu, p, 8);
        p += __shfl_xor_sync(0xffffffffu, p, 4);
        p += __shfl_xor_sync(0xffffffffu, p, 2);
        p += __shfl_xor_sync(0xffffffffu, p, 1);
        m = p; sum = 1.f; acc = vs;
    }

    auto update = [&](float l, float4 v) {
        float nm = fmaxf(m, l);
        float sc = __expf(m - nm);
        float e  = __expf(l - nm);
        sum = sum * sc + e;
        acc.x = acc.x * sc + e * v.x;
        acc.y = acc.y * sc + e * v.y;
        acc.z = acc.z * sc + e * v.z;
        acc.w = acc.w * sc + e * v.w;
        m = nm;
    };

    int j = beg;
    for (; j + 1 < end; j += 2) {
        int s0 = __ldg(&g_csr[j]);
        int s1 = __ldg(&g_csr[j + 1]);
        float4 v0 = *(const float4*)(g_xl2 + (size_t)s0 * OUTC + off);
        float4 v1 = *(const float4*)(g_xl2 + (size_t)s1 * OUTC + off);
        float p0 = partial(v0);
        float p1 = partial(v1);
#pragma unroll
        for (int d = 16; d >= 1; d >>= 1) {
            p0 += __shfl_xor_sync(0xffffffffu, p0, d);
            p1 += __shfl_xor_sync(0xffffffffu, p1, d);
        }
        update(p0, v0);
        update(p1, v1);
    }
    if (j < end) {
        int s0 = __ldg(&g_csr[j]);
        float4 v0 = *(const float4*)(g_xl2 + (size_t)s0 * OUTC + off);
        float p0 = partial(v0);
#pragma unroll
        for (int d = 16; d >= 1; d >>= 1)
            p0 += __shfl_xor_sync(0xffffffffu, p0, d);
        update(p0, v0);
    }

    float4 b = *(const float4*)(bias2 + off);
    float o0 = acc.x / sum + b.x;
    float o1 = acc.y / sum + b.y;
    float o2 = acc.z / sum + b.z;
    float o3 = acc.w / sum + b.w;
    bf16 h0, l0, h1, l1, h2, l2, h3, l3;
    split_bf16(o0, h0, l0); split_bf16(o1, h1, l1);
    split_bf16(o2, h2, l2); split_bf16(o3, h3, l3);
    __nv_bfloat162* ph = (__nv_bfloat162*)(g_Z2h + (size_t)n * OUTC + off);
    __nv_bfloat162* pl = (__nv_bfloat162*)(g_Z2l + (size_t)n * OUTC + off);
    ph[0] = {h0, h1}; ph[1] = {h2, h3};
    pl[0] = {l0, l1}; pl[1] = {l2, l3};
}

// ---------------- decoder edge kernel: out[e] = gelu(U[a]+V[b]).wd2 + bd2 ---
__global__ __launch_bounds__(256) void dec_edge(const int* __restrict__ eli,
                                                const float* __restrict__ wd2,
                                                const float* __restrict__ bd2,
                                                float* __restrict__ out)
{
    int e = (blockIdx.x * blockDim.x + threadIdx.x) >> 5;
    if (e >= ELL) return;
    int lane = threadIdx.x & 31;
    int a = __ldg(&eli[e]);
    int b = __ldg(&eli[ELL + e]);
    float4 u = *(const float4*)(g_U + (size_t)a * HIDC + lane * 4);
    float4 v = *(const float4*)(g_V + (size_t)b * HIDC + lane * 4);
    float4 w = *(const float4*)(wd2 + lane * 4);
    float s = gelu_t(u.x + v.x) * w.x + gelu_t(u.y + v.y) * w.y +
              gelu_t(u.z + v.z) * w.z + gelu_t(u.w + v.w) * w.w;
    s += __shfl_xor_sync(0xffffffffu, s, 16);
    s += __shfl_xor_sync(0xffffffffu, s, 8);
    s += __shfl_xor_sync(0xffffffffu, s, 4);
    s += __shfl_xor_sync(0xffffffffu, s, 2);
    s += __shfl_xor_sync(0xffffffffu, s, 1);
    if (lane == 0) out[e] = s + bd2[0];
}

// ---------------- launch ----------------------------------------------------
extern "C" void kernel_launch(void* const* d_in, const int* in_sizes, int n_in,
                              void* d_out, int out_size)
{
    const float* x     = (const float*)d_in[0];
    const int*   ei    = (const int*)d_in[1];
    const int*   eli   = (const int*)d_in[2];
    const float* W_l1  = (const float*)d_in[3];
    const float* b_l1  = (const float*)d_in[4];
    const float* W_r1  = (const float*)d_in[5];
    const float* b_r1  = (const float*)d_in[6];
    const float* att1  = (const float*)d_in[7];
    const float* bias1 = (const float*)d_in[8];
    const float* W_l2  = (const float*)d_in[9];
    const float* b_l2  = (const float*)d_in[10];
    const float* W_r2  = (const float*)d_in[11];
    const float* b_r2  = (const float*)d_in[12];
    const float* att2  = (const float*)d_in[13];
    const float* bias2 = (const float*)d_in[14];
    const float* W_d1  = (const float*)d_in[15];
    const float* b_d1  = (const float*)d_in[16];
    const float* W_d2  = (const float*)d_in[17];
    const float* b_d2  = (const float*)d_in[18];
    float* out = (float*)d_out;

    cudaFuncSetAttribute(gemm_mma, cudaFuncAttributeMaxDynamicSharedMemorySize, SMTOT);

    float *xl1, *xr1, *xl2, *xr2, *uu, *vv, *zr;
    bf16 *a1h, *a1l, *z2h, *z2l;
    bf16 *bt1lh, *bt1ll, *bt1rh, *bt1rl, *bt2lh, *bt2ll, *bt2rh, *bt2rl;
    bf16 *btd0h, *btd0l, *btd1h, *btd1l, *a2h, *a2l;
    cudaGetSymbolAddress((void**)&xl1,  g_xl1);
    cudaGetSymbolAddress((void**)&xr1,  g_xr1);
    cudaGetSymbolAddress((void**)&xl2,  g_xl2);
    cudaGetSymbolAddress((void**)&xr2,  g_xr2);
    cudaGetSymbolAddress((void**)&uu,   g_U);
    cudaGetSymbolAddress((void**)&vv,   g_V);
    cudaGetSymbolAddress((void**)&zr,   g_zero);
    cudaGetSymbolAddress((void**)&a1h,  g_A1h);
    cudaGetSymbolAddress((void**)&a1l,  g_A1l);
    cudaGetSymbolAddress((void**)&a2h,  g_A2h);
    cudaGetSymbolAddress((void**)&a2l,  g_A2l);
    cudaGetSymbolAddress((void**)&z2h,  g_Z2h);
    cudaGetSymbolAddress((void**)&z2l,  g_Z2l);
    cudaGetSymbolAddress((void**)&bt1lh, g_BT1lh);
    cudaGetSymbolAddress((void**)&bt1ll, g_BT1ll);
    cudaGetSymbolAddress((void**)&bt1rh, g_BT1rh);
    cudaGetSymbolAddress((void**)&bt1rl, g_BT1rl);
    cudaGetSymbolAddress((void**)&bt2lh, g_BT2lh);
    cudaGetSymbolAddress((void**)&bt2ll, g_BT2ll);
    cudaGetSymbolAddress((void**)&bt2rh, g_BT2rh);
    cudaGetSymbolAddress((void**)&bt2rl, g_BT2rl);
    cudaGetSymbolAddress((void**)&btd0h, g_BTd0h);
    cudaGetSymbolAddress((void**)&btd0l, g_BTd0l);
    cudaGetSymbolAddress((void**)&btd1h, g_BTd1h);
    cudaGetSymbolAddress((void**)&btd1l, g_BTd1l);

    // 0) prep (csr_zero fused into conv_x), ordered so gemm1 = launch index 3
    conv_x_kernel<<<(NN * INF_ / 4 + 255) / 256, 256>>>(x);     // idx 0
    csr_hist<<<(EE + 255) / 256, 256>>>(ei);                    // idx 1
    {
        dim3 grid(16, 16, 6), blk(32, 8);
        transpose_conv<<<grid, blk>>>(W_l1, W_r1, W_l2, W_r2, W_d1);  // idx 2
    }

    // 1) layer-1 transforms (launch index 3 -> profiled by ncu)
    {
        dim3 grid(2 * (C1 / 128), (NN + 127) / 128);
        gemm_mma<<<grid, 256, SMTOT>>>(a1h, a1l,
                                       bt1lh, bt1ll, bt1rh, bt1rl,
                                       b_l1, b_r1, xl1, xr1, NN, INF_, C1);
    }

    // 1b) finish CSR (needed only by gat kernels)
    csr_scan<<<1, 1024>>>();                                    // idx 4
    csr_fill<<<(EE + 255) / 256, 256>>>(ei);                    // idx 5

    // 2) layer-1 fused attention (online softmax, 2-edge unrolled)
    gat1_node<<<(NN * HH * 32 + 255) / 256, 256>>>(att1, bias1);

    // 3) layer-2 transforms
    {
        dim3 grid(2 * (OUTC / 128), (NN + 127) / 128);
        gemm_mma<<<grid, 256, SMTOT>>>(a2h, a2l,
                                       bt2lh, bt2ll, bt2rh, bt2rl,
                                       b_l2, b_r2, xl2, xr2, NN, C1, OUTC);
    }

    // 4) layer-2 fused attention
    gat2_node<<<(NN * 32 + 255) / 256, 256>>>(att2, bias2);

    // 5) decoder: per-node U = z@Wd1_top + bd1, V = z@Wd1_bot  (dual-B GEMM)
    {
        dim3 grid(2 * (HIDC / 128), (NN + 127) / 128);
        gemm_mma<<<grid, 256, SMTOT>>>(z2h, z2l,
                                       btd0h, btd0l, btd1h, btd1l,
                                       b_d1, zr, uu, vv, NN, OUTC, HIDC);
    }

    // 6) decoder edge kernel: out[e] = gelu(U[a]+V[b]).wd2 + bd2
    dec_edge<<<((ELL * 32) + 255) / 256, 256>>>(eli, W_d2, b_d2, out);
}